// round 9
// baseline (speedup 1.0000x reference)
#include <cuda_runtime.h>
#include <cuda_fp16.h>
#include <math.h>
#include <stdint.h>

// ===========================================================================
// ImplicitMap_fExtrator — fp16 3-term-split GEMM via mma.sync.m16n8k16.f16.
// Round 9: warp tile 64x64 (CTA 128x128, 4 warps, 2 CTAs/SM). LDSM:HMMA
// ratio 1:6 (was 1:4) — attacks issue-slot competition that capped tensor
// pipe at 56%. Kc=32 x 3 stages (96KB), 1 sync/iter, SW128 hi|lo-packed rows.
// ===========================================================================

#define NPTS   16384
#define NROWS  65536
#define PITCH  960

__device__ __half g_hiA[(size_t)NROWS * PITCH];
__device__ __half g_loA[(size_t)NROWS * PITCH];
__device__ __half g_hiB[(size_t)NROWS * PITCH];
__device__ __half g_loB[(size_t)NROWS * PITCH];
__device__ __half g_Whi[5600000];
__device__ __half g_Wlo[5600000];

static const int    LCIN [11] = {259,515,512,512,576,576,768,768,768,960,960};
static const int    LCOUT[11] = {515,512,512,576,576,768,768,768,960,960,896};
static const int    LPIT [11] = {264,520,512,512,576,576,768,768,768,960,960};
static const size_t LWOFF[11] = {0,135960,402200,664344,959256,1291032,1733400,
                                 2323224,2913048,3650328,4571928};

__device__ const int    d_LCIN [11] = {259,515,512,512,576,576,768,768,768,960,960};
__device__ const int    d_LCOUT[11] = {515,512,512,576,576,768,768,768,960,960,896};
__device__ const int    d_LPIT [11] = {264,520,512,512,576,576,768,768,768,960,960};
__device__ const size_t d_LWOFF[11] = {0,135960,402200,664344,959256,1291032,1733400,
                                       2323224,2913048,3650328,4571928};

// ---- PTX helpers ----------------------------------------------------------
__device__ __forceinline__ uint32_t smem_u32(const void* p) {
    uint32_t a;
    asm("{ .reg .u64 t; cvta.to.shared.u64 t, %1; cvt.u32.u64 %0, t; }"
        : "=r"(a) : "l"(p));
    return a;
}
__device__ __forceinline__ void cpa16(uint32_t dst, const void* src, int sz) {
    asm volatile("cp.async.cg.shared.global [%0], [%1], 16, %2;"
                 :: "r"(dst), "l"(src), "r"(sz));
}
__device__ __forceinline__ void cpa_commit() {
    asm volatile("cp.async.commit_group;" ::: "memory");
}
__device__ __forceinline__ void ldsm4(uint32_t* r, uint32_t a) {
    asm volatile("ldmatrix.sync.aligned.m8n8.x4.shared.b16 {%0,%1,%2,%3}, [%4];"
                 : "=r"(r[0]), "=r"(r[1]), "=r"(r[2]), "=r"(r[3]) : "r"(a));
}
__device__ __forceinline__ void mma_f16(float* d, const uint32_t* a,
                                        uint32_t b0, uint32_t b1) {
    asm volatile("mma.sync.aligned.m16n8k16.row.col.f32.f16.f16.f32 "
                 "{%0,%1,%2,%3}, {%4,%5,%6,%7}, {%8,%9}, {%0,%1,%2,%3};"
                 : "+f"(d[0]), "+f"(d[1]), "+f"(d[2]), "+f"(d[3])
                 : "r"(a[0]), "r"(a[1]), "r"(a[2]), "r"(a[3]),
                   "r"(b0), "r"(b1));
}
__device__ __forceinline__ void split2h(float v, __half& h, __half& l) {
    h = __float2half_rn(v);
    l = __float2half_rn(v - __half2float(h));
}

// ---- fused W prep ----------------------------------------------------------
struct WPtrs { const float* w[11]; };

__global__ void prep_all_kernel(WPtrs wp)
{
    int l = blockIdx.y;
    int idx = blockIdx.x * blockDim.x + threadIdx.x;
    int cin = d_LCIN[l];
    int cnt = cin * d_LCOUT[l];
    if (idx >= cnt) return;
    int row = idx / cin, col = idx - row * cin;
    __half h, lo;
    split2h(wp.w[l][idx], h, lo);
    size_t d = d_LWOFF[l] + (size_t)row * d_LPIT[l] + col;
    g_Whi[d] = h;
    g_Wlo[d] = lo;
}

// ---- init ------------------------------------------------------------------
__global__ void init_kernel(const float* __restrict__ inp,
                            const float* __restrict__ lat,
                            float* __restrict__ out_con)
{
    int idx = blockIdx.x * blockDim.x + threadIdx.x;   // NPTS*259
    if (idx >= NPTS * 259) return;
    int p = idx / 259;
    int c = idx - p * 259;
    int b = p >> 13;
    float v = (c < 3) ? inp[p * 3 + c] : lat[b * 256 + (c - 3)];
    out_con[idx] = v;
    size_t r0 = (size_t)(4 * p) * PITCH + c;
    __half h, l;
    split2h(v, h, l);
    g_hiA[r0] = h; g_loA[r0] = l;
    #pragma unroll
    for (int ch = 1; ch <= 3; ch++) {
        float gv = (c == ch - 1) ? 1.0f : 0.0f;
        size_t r = (size_t)(4 * p + ch) * PITCH + c;
        g_hiA[r] = __float2half_rn(gv);
        g_loA[r] = __float2half_rn(0.0f);
    }
}

// ---- fused layer: CTA 128x128, 4 warps (64x64 warp tile), Kc=32, 3 stages -
#define STAGES 3
#define A_OFF 0
#define B_OFF 16384
#define STG_SZ 32768
#define SMEM_BYTES (STAGES * STG_SZ)
#define SWZ(o) ((o) ^ (((o) >> 3) & 0x70))

__global__ void __launch_bounds__(128, 2)
layer_kernel(const float* __restrict__ bias, int cin, int cout,
             int wpitch, size_t woff, int flip)
{
    extern __shared__ char smem[];
    __shared__ float bias_s[128];
    const uint32_t sb = smem_u32(smem);
    const int t = threadIdx.x;
    const int lane = t & 31, wid = t >> 5;

    const __half* __restrict__ Xhi = flip ? g_hiB : g_hiA;
    const __half* __restrict__ Xlo = flip ? g_loB : g_loA;
    __half* __restrict__ Yhi = flip ? g_hiA : g_hiB;
    __half* __restrict__ Ylo = flip ? g_loA : g_loB;
    const __half* __restrict__ Wh = g_Whi + woff;
    const __half* __restrict__ Wl = g_Wlo + woff;

    const int cblk = blockIdx.x * 128;
    const int nblk = blockIdx.y * 128;

    {
        int c = cblk + t;
        bias_s[t] = (c < cout) ? __ldg(bias + c) : 0.f;
    }

    const int ktiles = (cin + 31) >> 5;

    // row layout: 128 rows x 128B ([hi 64B | lo 64B]), SW128 swizzle.
    // 1024 granules per tile, 8 per thread per tile (128 threads).
    auto load_stage = [&](int s, int kt) {
        const uint32_t base = sb + (uint32_t)s * STG_SZ;
        const int k0 = kt << 5;
        #pragma unroll
        for (int i = 0; i < 8; i++) {                  // A tile
            int li = t + (i << 7);
            int r = li >> 3, g = li & 7;
            int kk = k0 + (g & 3) * 8;
            int rem = cin - kk;
            int sz = rem >= 8 ? 16 : (rem > 0 ? rem * 2 : 0);
            const __half* src = (g < 4) ? Xhi : Xlo;
            cpa16(base + A_OFF + SWZ((uint32_t)(r * 128 + g * 16)),
                  src + (size_t)(nblk + r) * PITCH + kk, sz);
        }
        #pragma unroll
        for (int i = 0; i < 8; i++) {                  // B tile
            int li = t + (i << 7);
            int r = li >> 3, g = li & 7;
            int row = cblk + r;
            int kk = k0 + (g & 3) * 8;
            int rem = cin - kk;
            int sz = (row < cout) ? (rem >= 8 ? 16 : (rem > 0 ? rem * 2 : 0)) : 0;
            const __half* src = (g < 4) ? Wh : Wl;
            cpa16(base + B_OFF + SWZ((uint32_t)(r * 128 + g * 16)),
                  src + (size_t)row * wpitch + kk, sz);
        }
        cpa_commit();
    };

    // fragment addressing: warp tile 64(M) x 64(N); 2x2 warp grid
    const int wm = wid >> 1, wn = wid & 1;
    const int seg = lane >> 3, i7 = lane & 7;
    uint32_t aR[4], aX[4];
    #pragma unroll
    for (int mi = 0; mi < 4; mi++) {
        int r = wm * 64 + mi * 16 + (seg & 1) * 8 + i7;
        aR[mi] = (uint32_t)(r * 128);
        aX[mi] = (uint32_t)((r & 7) << 4);
    }
    const uint32_t akd = (uint32_t)((seg >> 1) * 16);
    uint32_t bR[4], bX[4];
    #pragma unroll
    for (int np = 0; np < 4; np++) {
        int r = wn * 64 + np * 16 + (seg >> 1) * 8 + i7;
        bR[np] = (uint32_t)(r * 128);
        bX[np] = (uint32_t)((r & 7) << 4);
    }
    const uint32_t bkd = (uint32_t)((seg & 1) * 16);

    float acc[4][8][4];
    #pragma unroll
    for (int mi = 0; mi < 4; mi++)
        #pragma unroll
        for (int ni = 0; ni < 8; ni++)
            #pragma unroll
            for (int r = 0; r < 4; r++) acc[mi][ni][r] = 0.f;

    auto compute = [&](int s) {
        const uint32_t base = sb + (uint32_t)s * STG_SZ;
        #pragma unroll
        for (int st = 0; st < 2; st++) {
            const uint32_t kb = (uint32_t)(st * 32);     // byte col in hi half
            uint32_t Ah[4][4], Bh[4][4];
            #pragma unroll
            for (int mi = 0; mi < 4; mi++)
                ldsm4(Ah[mi], base + A_OFF + aR[mi] + ((kb + akd) ^ aX[mi]));
            #pragma unroll
            for (int np = 0; np < 4; np++)
                ldsm4(Bh[np], base + B_OFF + bR[np] + ((kb + bkd) ^ bX[np]));
            #pragma unroll
            for (int mi = 0; mi < 4; mi++)
                #pragma unroll
                for (int ni = 0; ni < 8; ni++)
                    mma_f16(acc[mi][ni], Ah[mi],
                            Bh[ni >> 1][(ni & 1) * 2], Bh[ni >> 1][(ni & 1) * 2 + 1]);
            {   // term 2: Al*Bh (lo half at byte col +64)
                uint32_t Al[4][4];
                #pragma unroll
                for (int mi = 0; mi < 4; mi++)
                    ldsm4(Al[mi], base + A_OFF + aR[mi] + ((64 + kb + akd) ^ aX[mi]));
                #pragma unroll
                for (int mi = 0; mi < 4; mi++)
                    #pragma unroll
                    for (int ni = 0; ni < 8; ni++)
                        mma_f16(acc[mi][ni], Al[mi],
                                Bh[ni >> 1][(ni & 1) * 2], Bh[ni >> 1][(ni & 1) * 2 + 1]);
            }
            {   // term 3: Ah*Bl
                uint32_t Bl[4][4];
                #pragma unroll
                for (int np = 0; np < 4; np++)
                    ldsm4(Bl[np], base + B_OFF + bR[np] + ((64 + kb + bkd) ^ bX[np]));
                #pragma unroll
                for (int mi = 0; mi < 4; mi++)
                    #pragma unroll
                    for (int ni = 0; ni < 8; ni++)
                        mma_f16(acc[mi][ni], Ah[mi],
                                Bl[ni >> 1][(ni & 1) * 2], Bl[ni >> 1][(ni & 1) * 2 + 1]);
            }
        }
    };

    // ---- 3-stage pipeline, one barrier per iteration -----------------------
    load_stage(0, 0);
    if (ktiles > 1) load_stage(1, 1); else cpa_commit();
    for (int kt = 0; kt < ktiles; kt++) {
        asm volatile("cp.async.wait_group 1;" ::: "memory");
        __syncthreads();
        int nf = kt + 2;
        if (nf < ktiles) load_stage(nf % STAGES, nf); else cpa_commit();
        compute(kt % STAGES);
    }

    // ---- epilogue ----------------------------------------------------------
    const unsigned FULL = 0xffffffffu;
    const int srcl = lane & ~12;
    const bool is_x = (lane & 12) == 0;
    const int q = lane >> 2, c2 = (lane & 3) * 2;
    #pragma unroll
    for (int mi = 0; mi < 4; mi++) {
        int r0 = nblk + wm * 64 + mi * 16 + q;
        __half* yh0 = Yhi + (size_t)r0 * PITCH;
        __half* yl0 = Ylo + (size_t)r0 * PITCH;
        __half* yh1 = yh0 + (size_t)8 * PITCH;
        __half* yl1 = yl0 + (size_t)8 * PITCH;
        #pragma unroll
        for (int ni = 0; ni < 8; ni++) {
            int nloc = wn * 64 + ni * 8 + c2;
            int cg = cblk + nloc;
            float bv0 = bias_s[nloc], bv1 = bias_s[nloc + 1];
            const float* d = acc[mi][ni];
            #pragma unroll
            for (int rr = 0; rr < 2; rr++) {
                float d0 = d[rr * 2], d1 = d[rr * 2 + 1];
                float z0 = __shfl_sync(FULL, d0, srcl);
                float z1 = __shfl_sync(FULL, d1, srcl);
                float A0 = 100.f * (z0 + bv0);
                float A1 = 100.f * (z1 + bv1);
                float sp0 = 0.f, sg0 = 0.f, sp1 = 0.f, sg1 = 0.f;
                if (is_x) {
                    float e0 = __expf(-fabsf(A0)), e1 = __expf(-fabsf(A1));
                    sp0 = (fmaxf(A0, 0.f) + __logf(1.f + e0)) * 0.01f;
                    sp1 = (fmaxf(A1, 0.f) + __logf(1.f + e1)) * 0.01f;
                    float i0 = __fdividef(1.f, 1.f + e0);
                    float i1 = __fdividef(1.f, 1.f + e1);
                    sg0 = (A0 >= 0.f) ? i0 : e0 * i0;
                    sg1 = (A1 >= 0.f) ? i1 : e1 * i1;
                }
                sg0 = __shfl_sync(FULL, sg0, srcl);
                sg1 = __shfl_sync(FULL, sg1, srcl);
                float y0 = is_x ? sp0 : sg0 * d0;
                float y1 = is_x ? sp1 : sg1 * d1;
                __half h0, l0, h1, l1;
                split2h(y0, h0, l0);
                split2h(y1, h1, l1);
                __half* yh = rr ? yh1 : yh0;
                __half* yl = rr ? yl1 : yl0;
                if (cg + 1 < cout) {
                    uint32_t hp = (uint32_t)__half_as_ushort(h0)
                                | ((uint32_t)__half_as_ushort(h1) << 16);
                    uint32_t lp = (uint32_t)__half_as_ushort(l0)
                                | ((uint32_t)__half_as_ushort(l1) << 16);
                    *(uint32_t*)(yh + cg) = hp;
                    *(uint32_t*)(yl + cg) = lp;
                } else if (cg < cout) {
                    yh[cg] = h0;
                    yl[cg] = l0;
                }
            }
        }
    }
}

// ---- final layer: cout=1 dot product, warp per state row ------------------
__global__ void final_kernel(const float* __restrict__ W,
                             const float* __restrict__ bias,
                             float* __restrict__ out)
{
    int gw = (blockIdx.x * blockDim.x + threadIdx.x) >> 5;
    int lane = threadIdx.x & 31;
    if (gw >= NROWS) return;
    const __half* hp = g_hiB + (size_t)gw * PITCH;
    const __half* lp = g_loB + (size_t)gw * PITCH;
    float s = 0.f;
    for (int i = lane; i < 112; i += 32) {       // 112 * 8 = 896 channels
        uint4 hv = *(const uint4*)(hp + i * 8);
        uint4 lv = *(const uint4*)(lp + i * 8);
        float4 w0 = __ldg((const float4*)W + i * 2);
        float4 w1 = __ldg((const float4*)W + i * 2 + 1);
        const uint32_t* hw = &hv.x;
        const uint32_t* lw = &lv.x;
        float wf2[8] = {w0.x, w0.y, w0.z, w0.w, w1.x, w1.y, w1.z, w1.w};
        #pragma unroll
        for (int qq = 0; qq < 4; qq++) {
            float2 fh = __half22float2(*(const __half2*)&hw[qq]);
            float2 fl = __half22float2(*(const __half2*)&lw[qq]);
            s = fmaf(wf2[2 * qq],     fh.x + fl.x, s);
            s = fmaf(wf2[2 * qq + 1], fh.y + fl.y, s);
        }
    }
    #pragma unroll
    for (int o = 16; o; o >>= 1) s += __shfl_xor_sync(0xffffffffu, s, o);
    if (lane == 0) {
        int ch = gw & 3, p = gw >> 2;
        if (ch == 0) out[p] = s + bias[0];
        else         out[NPTS + 3 * (size_t)p + (ch - 1)] = s;
    }
}

// ---------------------------------------------------------------------------
extern "C" void kernel_launch(void* const* d_in, const int* in_sizes, int n_in,
                              void* d_out, int out_size)
{
    const float* input  = (const float*)d_in[0];
    const float* latent = (const float*)d_in[1];
    float* out = (float*)d_out;
    float* out_con = out + NPTS + NPTS * 3;

    {
        WPtrs wp;
        for (int l = 0; l < 11; l++) wp.w[l] = (const float*)d_in[2 + 2 * l];
        dim3 grid((960 * 960 + 255) / 256, 11);
        prep_all_kernel<<<grid, 256>>>(wp);
    }
    {
        int tot = NPTS * 259;
        init_kernel<<<(tot + 255) / 256, 256>>>(input, latent, out_con);
    }

    cudaFuncSetAttribute(layer_kernel,
                         cudaFuncAttributeMaxDynamicSharedMemorySize, SMEM_BYTES);

    for (int l = 0; l < 11; l++) {
        const float* b = (const float*)d_in[3 + 2 * l];
        dim3 grid((LCOUT[l] + 127) / 128, NROWS / 128);
        layer_kernel<<<grid, 128, SMEM_BYTES>>>(b, LCIN[l], LCOUT[l],
                                                LPIT[l], LWOFF[l], l & 1);
    }

    final_kernel<<<NROWS * 32 / 256, 256>>>((const float*)d_in[24],
                                            (const float*)d_in[25], out);
}

// round 10
// speedup vs baseline: 1.2493x; 1.2493x over previous
#include <cuda_runtime.h>
#include <cuda_fp16.h>
#include <math.h>
#include <stdint.h>

// ===========================================================================
// ImplicitMap_fExtrator — fp16 3-term-split GEMM via mma.sync.m16n8k16.
// Round 10: main term (Ah*Bh) in fp32 accumulators; correction terms
// (Al*Bh + Ah*Bl, ~2^-11 magnitude) share an fp16 accumulator — tests the
// "f32-acc HMMA is half-rate on the sm_103 legacy path" hypothesis.
// Base config = round 7 (best): Kc=32 x 3 stages, 64B-row tiles, 256 thr,
// warp tile 64x32, 1 sync/iter. Occupancy left to ptxas (~1 CTA/SM).
// ===========================================================================

#define NPTS   16384
#define NROWS  65536
#define PITCH  960

__device__ __half g_hiA[(size_t)NROWS * PITCH];
__device__ __half g_loA[(size_t)NROWS * PITCH];
__device__ __half g_hiB[(size_t)NROWS * PITCH];
__device__ __half g_loB[(size_t)NROWS * PITCH];
__device__ __half g_Whi[5600000];
__device__ __half g_Wlo[5600000];

static const int    LCIN [11] = {259,515,512,512,576,576,768,768,768,960,960};
static const int    LCOUT[11] = {515,512,512,576,576,768,768,768,960,960,896};
static const int    LPIT [11] = {264,520,512,512,576,576,768,768,768,960,960};
static const size_t LWOFF[11] = {0,135960,402200,664344,959256,1291032,1733400,
                                 2323224,2913048,3650328,4571928};

__device__ const int    d_LCIN [11] = {259,515,512,512,576,576,768,768,768,960,960};
__device__ const int    d_LCOUT[11] = {515,512,512,576,576,768,768,768,960,960,896};
__device__ const int    d_LPIT [11] = {264,520,512,512,576,576,768,768,768,960,960};
__device__ const size_t d_LWOFF[11] = {0,135960,402200,664344,959256,1291032,1733400,
                                       2323224,2913048,3650328,4571928};

// ---- PTX helpers ----------------------------------------------------------
__device__ __forceinline__ uint32_t smem_u32(const void* p) {
    uint32_t a;
    asm("{ .reg .u64 t; cvta.to.shared.u64 t, %1; cvt.u32.u64 %0, t; }"
        : "=r"(a) : "l"(p));
    return a;
}
__device__ __forceinline__ void cpa16(uint32_t dst, const void* src, int sz) {
    asm volatile("cp.async.cg.shared.global [%0], [%1], 16, %2;"
                 :: "r"(dst), "l"(src), "r"(sz));
}
__device__ __forceinline__ void cpa_commit() {
    asm volatile("cp.async.commit_group;" ::: "memory");
}
__device__ __forceinline__ void ldsm4(uint32_t* r, uint32_t a) {
    asm volatile("ldmatrix.sync.aligned.m8n8.x4.shared.b16 {%0,%1,%2,%3}, [%4];"
                 : "=r"(r[0]), "=r"(r[1]), "=r"(r[2]), "=r"(r[3]) : "r"(a));
}
// fp32-accumulator mma (main term)
__device__ __forceinline__ void mma_f16(float* d, const uint32_t* a,
                                        uint32_t b0, uint32_t b1) {
    asm volatile("mma.sync.aligned.m16n8k16.row.col.f32.f16.f16.f32 "
                 "{%0,%1,%2,%3}, {%4,%5,%6,%7}, {%8,%9}, {%0,%1,%2,%3};"
                 : "+f"(d[0]), "+f"(d[1]), "+f"(d[2]), "+f"(d[3])
                 : "r"(a[0]), "r"(a[1]), "r"(a[2]), "r"(a[3]),
                   "r"(b0), "r"(b1));
}
// fp16-accumulator mma (correction terms, ~2^-11 magnitude)
__device__ __forceinline__ void mma_f16acc(uint32_t* d, const uint32_t* a,
                                           uint32_t b0, uint32_t b1) {
    asm volatile("mma.sync.aligned.m16n8k16.row.col.f16.f16.f16.f16 "
                 "{%0,%1}, {%2,%3,%4,%5}, {%6,%7}, {%0,%1};"
                 : "+r"(d[0]), "+r"(d[1])
                 : "r"(a[0]), "r"(a[1]), "r"(a[2]), "r"(a[3]),
                   "r"(b0), "r"(b1));
}
__device__ __forceinline__ void split2h(float v, __half& h, __half& l) {
    h = __float2half_rn(v);
    l = __float2half_rn(v - __half2float(h));
}

// ---- fused W prep ----------------------------------------------------------
struct WPtrs { const float* w[11]; };

__global__ void prep_all_kernel(WPtrs wp)
{
    int l = blockIdx.y;
    int idx = blockIdx.x * blockDim.x + threadIdx.x;
    int cin = d_LCIN[l];
    int cnt = cin * d_LCOUT[l];
    if (idx >= cnt) return;
    int row = idx / cin, col = idx - row * cin;
    __half h, lo;
    split2h(wp.w[l][idx], h, lo);
    size_t d = d_LWOFF[l] + (size_t)row * d_LPIT[l] + col;
    g_Whi[d] = h;
    g_Wlo[d] = lo;
}

// ---- init ------------------------------------------------------------------
__global__ void init_kernel(const float* __restrict__ inp,
                            const float* __restrict__ lat,
                            float* __restrict__ out_con)
{
    int idx = blockIdx.x * blockDim.x + threadIdx.x;   // NPTS*259
    if (idx >= NPTS * 259) return;
    int p = idx / 259;
    int c = idx - p * 259;
    int b = p >> 13;
    float v = (c < 3) ? inp[p * 3 + c] : lat[b * 256 + (c - 3)];
    out_con[idx] = v;
    size_t r0 = (size_t)(4 * p) * PITCH + c;
    __half h, l;
    split2h(v, h, l);
    g_hiA[r0] = h; g_loA[r0] = l;
    #pragma unroll
    for (int ch = 1; ch <= 3; ch++) {
        float gv = (c == ch - 1) ? 1.0f : 0.0f;
        size_t r = (size_t)(4 * p + ch) * PITCH + c;
        g_hiA[r] = __float2half_rn(gv);
        g_loA[r] = __float2half_rn(0.0f);
    }
}

// ---- fused layer: CTA 128x128, Kc=32, 3 stages, 1 sync/iter ---------------
#define STAGES 3
#define AHI 0
#define ALO 8192
#define BHI 16384
#define BLO 24576
#define STG_SZ 32768
#define SMEM_BYTES (STAGES * STG_SZ)
#define SWZ64(o) ((o) ^ (((o) >> 3) & 0x30))

__global__ void __launch_bounds__(256)
layer_kernel(const float* __restrict__ bias, int cin, int cout,
             int wpitch, size_t woff, int flip)
{
    extern __shared__ char smem[];
    __shared__ float bias_s[128];
    const uint32_t sb = smem_u32(smem);
    const int t = threadIdx.x;
    const int lane = t & 31, wid = t >> 5;

    const __half* __restrict__ Xhi = flip ? g_hiB : g_hiA;
    const __half* __restrict__ Xlo = flip ? g_loB : g_loA;
    __half* __restrict__ Yhi = flip ? g_hiA : g_hiB;
    __half* __restrict__ Ylo = flip ? g_loA : g_loB;
    const __half* __restrict__ Wh = g_Whi + woff;
    const __half* __restrict__ Wl = g_Wlo + woff;

    const int cblk = blockIdx.x * 128;
    const int nblk = blockIdx.y * 128;

    if (t < 128) {
        int c = cblk + t;
        bias_s[t] = (c < cout) ? __ldg(bias + c) : 0.f;
    }

    const int ktiles = (cin + 31) >> 5;

    auto load_stage = [&](int s, int kt) {
        const uint32_t base = sb + (uint32_t)s * STG_SZ;
        const int k0 = kt << 5;
        #pragma unroll
        for (int i = 0; i < 2; i++) {              // A: 512 granules x2 arrays
            int li = t + (i << 8);
            int r = li >> 2, g = li & 3;
            int kk = k0 + g * 8, rem = cin - kk;
            int sz = rem >= 8 ? 16 : (rem > 0 ? rem * 2 : 0);
            uint32_t o = SWZ64((uint32_t)(r * 64 + g * 16));
            const size_t so = (size_t)(nblk + r) * PITCH + kk;
            cpa16(base + AHI + o, Xhi + so, sz);
            cpa16(base + ALO + o, Xlo + so, sz);
        }
        #pragma unroll
        for (int i = 0; i < 2; i++) {              // B: 512 granules x2 arrays
            int li = t + (i << 8);
            int r = li >> 2, g = li & 3;
            int row = cblk + r;
            int kk = k0 + g * 8, rem = cin - kk;
            int sz = (row < cout) ? (rem >= 8 ? 16 : (rem > 0 ? rem * 2 : 0)) : 0;
            uint32_t o = SWZ64((uint32_t)(r * 64 + g * 16));
            const size_t so = (size_t)row * wpitch + kk;
            cpa16(base + BHI + o, Wh + so, sz);
            cpa16(base + BLO + o, Wl + so, sz);
        }
        cpa_commit();
    };

    // fragment addressing (64B rows, XOR-swizzled) — round-4-validated
    const int wm = wid >> 2, wn = wid & 3;       // warp tile 64(M) x 32(N)
    const int seg = lane >> 3, i7 = lane & 7;
    uint32_t aR[4], aX[4];
    #pragma unroll
    for (int mi = 0; mi < 4; mi++) {
        int r = wm * 64 + mi * 16 + (seg & 1) * 8 + i7;
        aR[mi] = (uint32_t)(r * 64);
        aX[mi] = (aR[mi] >> 3) & 0x30;
    }
    const uint32_t akd = (uint32_t)((seg >> 1) * 16);
    uint32_t bR[2], bX[2];
    #pragma unroll
    for (int np = 0; np < 2; np++) {
        int r = wn * 32 + np * 16 + (seg >> 1) * 8 + i7;
        bR[np] = (uint32_t)(r * 64);
        bX[np] = (bR[np] >> 3) & 0x30;
    }
    const uint32_t bkd = (uint32_t)((seg & 1) * 16);

    float acc[4][4][4];               // fp32 main-term accumulators
    uint32_t accL[4][4][2];           // fp16 correction-term accumulators
    #pragma unroll
    for (int mi = 0; mi < 4; mi++)
        #pragma unroll
        for (int ni = 0; ni < 4; ni++) {
            #pragma unroll
            for (int r = 0; r < 4; r++) acc[mi][ni][r] = 0.f;
            accL[mi][ni][0] = 0u;
            accL[mi][ni][1] = 0u;
        }

    auto compute = [&](int s) {
        const uint32_t base = sb + (uint32_t)s * STG_SZ;
        #pragma unroll
        for (int st = 0; st < 2; st++) {
            const uint32_t kb = (uint32_t)(st * 32);
            uint32_t Ah[4][4], Bh[2][4];
            #pragma unroll
            for (int mi = 0; mi < 4; mi++)
                ldsm4(Ah[mi], base + AHI + aR[mi] + ((kb + akd) ^ aX[mi]));
            #pragma unroll
            for (int np = 0; np < 2; np++)
                ldsm4(Bh[np], base + BHI + bR[np] + ((kb + bkd) ^ bX[np]));
            // main term: fp32 acc
            #pragma unroll
            for (int mi = 0; mi < 4; mi++)
                #pragma unroll
                for (int ni = 0; ni < 4; ni++)
                    mma_f16(acc[mi][ni], Ah[mi],
                            Bh[ni >> 1][(ni & 1) * 2], Bh[ni >> 1][(ni & 1) * 2 + 1]);
            {   // correction term 2: Al*Bh (fp16 acc)
                uint32_t Al[4][4];
                #pragma unroll
                for (int mi = 0; mi < 4; mi++)
                    ldsm4(Al[mi], base + ALO + aR[mi] + ((kb + akd) ^ aX[mi]));
                #pragma unroll
                for (int mi = 0; mi < 4; mi++)
                    #pragma unroll
                    for (int ni = 0; ni < 4; ni++)
                        mma_f16acc(accL[mi][ni], Al[mi],
                                   Bh[ni >> 1][(ni & 1) * 2], Bh[ni >> 1][(ni & 1) * 2 + 1]);
            }
            {   // correction term 3: Ah*Bl (fp16 acc)
                uint32_t Bl[2][4];
                #pragma unroll
                for (int np = 0; np < 2; np++)
                    ldsm4(Bl[np], base + BLO + bR[np] + ((kb + bkd) ^ bX[np]));
                #pragma unroll
                for (int mi = 0; mi < 4; mi++)
                    #pragma unroll
                    for (int ni = 0; ni < 4; ni++)
                        mma_f16acc(accL[mi][ni], Ah[mi],
                                   Bl[ni >> 1][(ni & 1) * 2], Bl[ni >> 1][(ni & 1) * 2 + 1]);
            }
        }
    };

    // ---- 3-stage pipeline, one barrier per iteration -----------------------
    load_stage(0, 0);
    if (ktiles > 1) load_stage(1, 1); else cpa_commit();
    for (int kt = 0; kt < ktiles; kt++) {
        asm volatile("cp.async.wait_group 1;" ::: "memory");
        __syncthreads();
        int nf = kt + 2;
        if (nf < ktiles) load_stage(nf % STAGES, nf); else cpa_commit();
        compute(kt % STAGES);
    }

    // ---- epilogue ----------------------------------------------------------
    const unsigned FULL = 0xffffffffu;
    const int srcl = lane & ~12;
    const bool is_x = (lane & 12) == 0;
    const int q = lane >> 2, c2 = (lane & 3) * 2;
    #pragma unroll
    for (int mi = 0; mi < 4; mi++) {
        int r0 = nblk + wm * 64 + mi * 16 + q;
        __half* yh0 = Yhi + (size_t)r0 * PITCH;
        __half* yl0 = Ylo + (size_t)r0 * PITCH;
        __half* yh1 = yh0 + (size_t)8 * PITCH;
        __half* yl1 = yl0 + (size_t)8 * PITCH;
        #pragma unroll
        for (int ni = 0; ni < 4; ni++) {
            int nloc = wn * 32 + ni * 8 + c2;
            int cg = cblk + nloc;
            float bv0 = bias_s[nloc], bv1 = bias_s[nloc + 1];
            // merge fp16 correction accumulator into fp32 main
            float2 lo01 = __half22float2(*(const __half2*)&accL[mi][ni][0]);
            float2 lo23 = __half22float2(*(const __half2*)&accL[mi][ni][1]);
            float dd[4];
            dd[0] = acc[mi][ni][0] + lo01.x;
            dd[1] = acc[mi][ni][1] + lo01.y;
            dd[2] = acc[mi][ni][2] + lo23.x;
            dd[3] = acc[mi][ni][3] + lo23.y;
            #pragma unroll
            for (int rr = 0; rr < 2; rr++) {
                float d0 = dd[rr * 2], d1 = dd[rr * 2 + 1];
                float z0 = __shfl_sync(FULL, d0, srcl);
                float z1 = __shfl_sync(FULL, d1, srcl);
                float A0 = 100.f * (z0 + bv0);
                float A1 = 100.f * (z1 + bv1);
                float sp0 = 0.f, sg0 = 0.f, sp1 = 0.f, sg1 = 0.f;
                if (is_x) {
                    float e0 = __expf(-fabsf(A0)), e1 = __expf(-fabsf(A1));
                    sp0 = (fmaxf(A0, 0.f) + __logf(1.f + e0)) * 0.01f;
                    sp1 = (fmaxf(A1, 0.f) + __logf(1.f + e1)) * 0.01f;
                    float i0 = __fdividef(1.f, 1.f + e0);
                    float i1 = __fdividef(1.f, 1.f + e1);
                    sg0 = (A0 >= 0.f) ? i0 : e0 * i0;
                    sg1 = (A1 >= 0.f) ? i1 : e1 * i1;
                }
                sg0 = __shfl_sync(FULL, sg0, srcl);
                sg1 = __shfl_sync(FULL, sg1, srcl);
                float y0 = is_x ? sp0 : sg0 * d0;
                float y1 = is_x ? sp1 : sg1 * d1;
                __half h0, l0, h1, l1;
                split2h(y0, h0, l0);
                split2h(y1, h1, l1);
                __half* yh = rr ? yh1 : yh0;
                __half* yl = rr ? yl1 : yl0;
                if (cg + 1 < cout) {
                    uint32_t hp = (uint32_t)__half_as_ushort(h0)
                                | ((uint32_t)__half_as_ushort(h1) << 16);
                    uint32_t lp = (uint32_t)__half_as_ushort(l0)
                                | ((uint32_t)__half_as_ushort(l1) << 16);
                    *(uint32_t*)(yh + cg) = hp;
                    *(uint32_t*)(yl + cg) = lp;
                } else if (cg < cout) {
                    yh[cg] = h0;
                    yl[cg] = l0;
                }
            }
        }
    }
}

// ---- final layer: cout=1 dot product, warp per state row ------------------
__global__ void final_kernel(const float* __restrict__ W,
                             const float* __restrict__ bias,
                             float* __restrict__ out)
{
    int gw = (blockIdx.x * blockDim.x + threadIdx.x) >> 5;
    int lane = threadIdx.x & 31;
    if (gw >= NROWS) return;
    const __half* hp = g_hiB + (size_t)gw * PITCH;
    const __half* lp = g_loB + (size_t)gw * PITCH;
    float s = 0.f;
    for (int i = lane; i < 112; i += 32) {       // 112 * 8 = 896 channels
        uint4 hv = *(const uint4*)(hp + i * 8);
        uint4 lv = *(const uint4*)(lp + i * 8);
        float4 w0 = __ldg((const float4*)W + i * 2);
        float4 w1 = __ldg((const float4*)W + i * 2 + 1);
        const uint32_t* hw = &hv.x;
        const uint32_t* lw = &lv.x;
        float wf2[8] = {w0.x, w0.y, w0.z, w0.w, w1.x, w1.y, w1.z, w1.w};
        #pragma unroll
        for (int qq = 0; qq < 4; qq++) {
            float2 fh = __half22float2(*(const __half2*)&hw[qq]);
            float2 fl = __half22float2(*(const __half2*)&lw[qq]);
            s = fmaf(wf2[2 * qq],     fh.x + fl.x, s);
            s = fmaf(wf2[2 * qq + 1], fh.y + fl.y, s);
        }
    }
    #pragma unroll
    for (int o = 16; o; o >>= 1) s += __shfl_xor_sync(0xffffffffu, s, o);
    if (lane == 0) {
        int ch = gw & 3, p = gw >> 2;
        if (ch == 0) out[p] = s + bias[0];
        else         out[NPTS + 3 * (size_t)p + (ch - 1)] = s;
    }
}

// ---------------------------------------------------------------------------
extern "C" void kernel_launch(void* const* d_in, const int* in_sizes, int n_in,
                              void* d_out, int out_size)
{
    const float* input  = (const float*)d_in[0];
    const float* latent = (const float*)d_in[1];
    float* out = (float*)d_out;
    float* out_con = out + NPTS + NPTS * 3;

    {
        WPtrs wp;
        for (int l = 0; l < 11; l++) wp.w[l] = (const float*)d_in[2 + 2 * l];
        dim3 grid((960 * 960 + 255) / 256, 11);
        prep_all_kernel<<<grid, 256>>>(wp);
    }
    {
        int tot = NPTS * 259;
        init_kernel<<<(tot + 255) / 256, 256>>>(input, latent, out_con);
    }

    cudaFuncSetAttribute(layer_kernel,
                         cudaFuncAttributeMaxDynamicSharedMemorySize, SMEM_BYTES);

    for (int l = 0; l < 11; l++) {
        const float* b = (const float*)d_in[3 + 2 * l];
        dim3 grid((LCOUT[l] + 127) / 128, NROWS / 128);
        layer_kernel<<<grid, 256, SMEM_BYTES>>>(b, LCIN[l], LCOUT[l],
                                                LPIT[l], LWOFF[l], l & 1);
    }

    final_kernel<<<NROWS * 32 / 256, 256>>>((const float*)d_in[24],
                                            (const float*)d_in[25], out);
}

// round 11
// speedup vs baseline: 1.7840x; 1.4280x over previous
#include <cuda_runtime.h>
#include <cuda_fp16.h>
#include <math.h>
#include <stdint.h>

// ===========================================================================
// ImplicitMap_fExtrator — Round 11: x/g split GEMMs (legacy HMMA at its
// ~325 TF/s ceiling -> only FLOP reduction helps).
//   x-path (16384 rows): 3-term fp16 hi/lo split (gate-critical precision).
//     epilogue: z=D+b, x'=softplus(100z)/100, sigma=sigmoid(100z) -> fp32 gate buf.
//   g-path (49152 rows, 3 per point): 2-term (Whi+Wlo)*ghi, g stored single
//     fp16. epilogue: g' = gate[p][c] * D. No bias, no transcendentals.
// FLOPs: 0.25*3 + 0.75*2 = 2.25 vs 3.0 units (-25%).
// GEMM core = round-7 best config: Kc=32 x 3 stages, 64B-row XOR tiles,
// 256 thr, warp tile 64x32, 1 sync/iter, 2 CTAs/SM.
// ===========================================================================

#define NPTS   16384
#define NGR    49152          // 3 * NPTS gradient rows
#define PITCH  960

__device__ __half g_xhiA[(size_t)NPTS * PITCH];
__device__ __half g_xloA[(size_t)NPTS * PITCH];
__device__ __half g_xhiB[(size_t)NPTS * PITCH];
__device__ __half g_xloB[(size_t)NPTS * PITCH];
__device__ __half g_ghiA[(size_t)NGR * PITCH];
__device__ __half g_ghiB[(size_t)NGR * PITCH];
__device__ float  g_gate[(size_t)NPTS * PITCH];
__device__ __half g_Whi[5600000];
__device__ __half g_Wlo[5600000];

static const int    LCIN [11] = {259,515,512,512,576,576,768,768,768,960,960};
static const int    LCOUT[11] = {515,512,512,576,576,768,768,768,960,960,896};
static const int    LPIT [11] = {264,520,512,512,576,576,768,768,768,960,960};
static const size_t LWOFF[11] = {0,135960,402200,664344,959256,1291032,1733400,
                                 2323224,2913048,3650328,4571928};

__device__ const int    d_LCIN [11] = {259,515,512,512,576,576,768,768,768,960,960};
__device__ const int    d_LCOUT[11] = {515,512,512,576,576,768,768,768,960,960,896};
__device__ const int    d_LPIT [11] = {264,520,512,512,576,576,768,768,768,960,960};
__device__ const size_t d_LWOFF[11] = {0,135960,402200,664344,959256,1291032,1733400,
                                       2323224,2913048,3650328,4571928};

// ---- PTX helpers ----------------------------------------------------------
__device__ __forceinline__ uint32_t smem_u32(const void* p) {
    uint32_t a;
    asm("{ .reg .u64 t; cvta.to.shared.u64 t, %1; cvt.u32.u64 %0, t; }"
        : "=r"(a) : "l"(p));
    return a;
}
__device__ __forceinline__ void cpa16(uint32_t dst, const void* src, int sz) {
    asm volatile("cp.async.cg.shared.global [%0], [%1], 16, %2;"
                 :: "r"(dst), "l"(src), "r"(sz));
}
__device__ __forceinline__ void cpa_commit() {
    asm volatile("cp.async.commit_group;" ::: "memory");
}
__device__ __forceinline__ void ldsm4(uint32_t* r, uint32_t a) {
    asm volatile("ldmatrix.sync.aligned.m8n8.x4.shared.b16 {%0,%1,%2,%3}, [%4];"
                 : "=r"(r[0]), "=r"(r[1]), "=r"(r[2]), "=r"(r[3]) : "r"(a));
}
__device__ __forceinline__ void mma_f16(float* d, const uint32_t* a,
                                        uint32_t b0, uint32_t b1) {
    asm volatile("mma.sync.aligned.m16n8k16.row.col.f32.f16.f16.f32 "
                 "{%0,%1,%2,%3}, {%4,%5,%6,%7}, {%8,%9}, {%0,%1,%2,%3};"
                 : "+f"(d[0]), "+f"(d[1]), "+f"(d[2]), "+f"(d[3])
                 : "r"(a[0]), "r"(a[1]), "r"(a[2]), "r"(a[3]),
                   "r"(b0), "r"(b1));
}
__device__ __forceinline__ void split2h(float v, __half& h, __half& l) {
    h = __float2half_rn(v);
    l = __float2half_rn(v - __half2float(h));
}

// ---- fused W prep ----------------------------------------------------------
struct WPtrs { const float* w[11]; };

__global__ void prep_all_kernel(WPtrs wp)
{
    int l = blockIdx.y;
    int idx = blockIdx.x * blockDim.x + threadIdx.x;
    int cin = d_LCIN[l];
    int cnt = cin * d_LCOUT[l];
    if (idx >= cnt) return;
    int row = idx / cin, col = idx - row * cin;
    __half h, lo;
    split2h(wp.w[l][idx], h, lo);
    size_t d = d_LWOFF[l] + (size_t)row * d_LPIT[l] + col;
    g_Whi[d] = h;
    g_Wlo[d] = lo;
}

// ---- init: x-state split, g-state identity seed, input_con ----------------
__global__ void init_kernel(const float* __restrict__ inp,
                            const float* __restrict__ lat,
                            float* __restrict__ out_con)
{
    int idx = blockIdx.x * blockDim.x + threadIdx.x;   // NPTS*259
    if (idx >= NPTS * 259) return;
    int p = idx / 259;
    int c = idx - p * 259;
    int b = p >> 13;
    float v = (c < 3) ? inp[p * 3 + c] : lat[b * 256 + (c - 3)];
    out_con[idx] = v;
    __half h, l;
    split2h(v, h, l);
    size_t xo = (size_t)p * PITCH + c;
    g_xhiA[xo] = h;
    g_xloA[xo] = l;
    #pragma unroll
    for (int ci = 0; ci < 3; ci++) {
        g_ghiA[(size_t)(3 * p + ci) * PITCH + c] =
            __float2half_rn((c == ci) ? 1.0f : 0.0f);
    }
}

// ===========================================================================
// x-layer kernel: 3-term split GEMM on 16384 x-rows.
// ===========================================================================
#define STAGES 3
#define XAHI 0
#define XALO 8192
#define XBHI 16384
#define XBLO 24576
#define STG_X 32768
#define SMEM_X (STAGES * STG_X)
#define SWZ64(o) ((o) ^ (((o) >> 3) & 0x30))

__global__ void __launch_bounds__(256, 2)
layer_x_kernel(const float* __restrict__ bias, int cin, int cout,
               int wpitch, size_t woff, int flip)
{
    extern __shared__ char smem[];
    __shared__ float bias_s[128];
    const uint32_t sb = smem_u32(smem);
    const int t = threadIdx.x;
    const int lane = t & 31, wid = t >> 5;

    const __half* __restrict__ Xhi = flip ? g_xhiB : g_xhiA;
    const __half* __restrict__ Xlo = flip ? g_xloB : g_xloA;
    __half* __restrict__ Yhi = flip ? g_xhiA : g_xhiB;
    __half* __restrict__ Ylo = flip ? g_xloA : g_xloB;
    const __half* __restrict__ Wh = g_Whi + woff;
    const __half* __restrict__ Wl = g_Wlo + woff;

    const int cblk = blockIdx.x * 128;
    const int nblk = blockIdx.y * 128;

    if (t < 128) {
        int c = cblk + t;
        bias_s[t] = (c < cout) ? __ldg(bias + c) : 0.f;
    }

    const int ktiles = (cin + 31) >> 5;

    auto load_stage = [&](int s, int kt) {
        const uint32_t base = sb + (uint32_t)s * STG_X;
        const int k0 = kt << 5;
        #pragma unroll
        for (int i = 0; i < 2; i++) {
            int li = t + (i << 8);
            int r = li >> 2, g = li & 3;
            int kk = k0 + g * 8, rem = cin - kk;
            int sz = rem >= 8 ? 16 : (rem > 0 ? rem * 2 : 0);
            uint32_t o = SWZ64((uint32_t)(r * 64 + g * 16));
            const size_t so = (size_t)(nblk + r) * PITCH + kk;
            cpa16(base + XAHI + o, Xhi + so, sz);
            cpa16(base + XALO + o, Xlo + so, sz);
        }
        #pragma unroll
        for (int i = 0; i < 2; i++) {
            int li = t + (i << 8);
            int r = li >> 2, g = li & 3;
            int row = cblk + r;
            int kk = k0 + g * 8, rem = cin - kk;
            int sz = (row < cout) ? (rem >= 8 ? 16 : (rem > 0 ? rem * 2 : 0)) : 0;
            uint32_t o = SWZ64((uint32_t)(r * 64 + g * 16));
            const size_t so = (size_t)row * wpitch + kk;
            cpa16(base + XBHI + o, Wh + so, sz);
            cpa16(base + XBLO + o, Wl + so, sz);
        }
        cpa_commit();
    };

    const int wm = wid >> 2, wn = wid & 3;       // warp tile 64(M) x 32(N)
    const int seg = lane >> 3, i7 = lane & 7;
    uint32_t aR[4], aX[4];
    #pragma unroll
    for (int mi = 0; mi < 4; mi++) {
        int r = wm * 64 + mi * 16 + (seg & 1) * 8 + i7;
        aR[mi] = (uint32_t)(r * 64);
        aX[mi] = (aR[mi] >> 3) & 0x30;
    }
    const uint32_t akd = (uint32_t)((seg >> 1) * 16);
    uint32_t bR[2], bX[2];
    #pragma unroll
    for (int np = 0; np < 2; np++) {
        int r = wn * 32 + np * 16 + (seg >> 1) * 8 + i7;
        bR[np] = (uint32_t)(r * 64);
        bX[np] = (bR[np] >> 3) & 0x30;
    }
    const uint32_t bkd = (uint32_t)((seg & 1) * 16);

    float acc[4][4][4];
    #pragma unroll
    for (int mi = 0; mi < 4; mi++)
        #pragma unroll
        for (int ni = 0; ni < 4; ni++)
            #pragma unroll
            for (int r = 0; r < 4; r++) acc[mi][ni][r] = 0.f;

    auto compute = [&](int s) {
        const uint32_t base = sb + (uint32_t)s * STG_X;
        #pragma unroll
        for (int st = 0; st < 2; st++) {
            const uint32_t kb = (uint32_t)(st * 32);
            uint32_t Ah[4][4], Bh[2][4];
            #pragma unroll
            for (int mi = 0; mi < 4; mi++)
                ldsm4(Ah[mi], base + XAHI + aR[mi] + ((kb + akd) ^ aX[mi]));
            #pragma unroll
            for (int np = 0; np < 2; np++)
                ldsm4(Bh[np], base + XBHI + bR[np] + ((kb + bkd) ^ bX[np]));
            #pragma unroll
            for (int mi = 0; mi < 4; mi++)
                #pragma unroll
                for (int ni = 0; ni < 4; ni++)
                    mma_f16(acc[mi][ni], Ah[mi],
                            Bh[ni >> 1][(ni & 1) * 2], Bh[ni >> 1][(ni & 1) * 2 + 1]);
            {
                uint32_t Al[4][4];
                #pragma unroll
                for (int mi = 0; mi < 4; mi++)
                    ldsm4(Al[mi], base + XALO + aR[mi] + ((kb + akd) ^ aX[mi]));
                #pragma unroll
                for (int mi = 0; mi < 4; mi++)
                    #pragma unroll
                    for (int ni = 0; ni < 4; ni++)
                        mma_f16(acc[mi][ni], Al[mi],
                                Bh[ni >> 1][(ni & 1) * 2], Bh[ni >> 1][(ni & 1) * 2 + 1]);
            }
            {
                uint32_t Bl[2][4];
                #pragma unroll
                for (int np = 0; np < 2; np++)
                    ldsm4(Bl[np], base + XBLO + bR[np] + ((kb + bkd) ^ bX[np]));
                #pragma unroll
                for (int mi = 0; mi < 4; mi++)
                    #pragma unroll
                    for (int ni = 0; ni < 4; ni++)
                        mma_f16(acc[mi][ni], Ah[mi],
                                Bl[ni >> 1][(ni & 1) * 2], Bl[ni >> 1][(ni & 1) * 2 + 1]);
            }
        }
    };

    load_stage(0, 0);
    if (ktiles > 1) load_stage(1, 1); else cpa_commit();
    for (int kt = 0; kt < ktiles; kt++) {
        asm volatile("cp.async.wait_group 1;" ::: "memory");
        __syncthreads();
        int nf = kt + 2;
        if (nf < ktiles) load_stage(nf % STAGES, nf); else cpa_commit();
        compute(kt % STAGES);
    }

    // epilogue: per-element softplus + sigma; write xhi/xlo + gate (fp32)
    const int q = lane >> 2, c2 = (lane & 3) * 2;
    #pragma unroll
    for (int mi = 0; mi < 4; mi++) {
        int r0 = nblk + wm * 64 + mi * 16 + q;
        #pragma unroll
        for (int ni = 0; ni < 4; ni++) {
            int nloc = wn * 32 + ni * 8 + c2;
            int cg = cblk + nloc;
            float bv0 = bias_s[nloc], bv1 = bias_s[nloc + 1];
            const float* d = acc[mi][ni];
            #pragma unroll
            for (int rr = 0; rr < 2; rr++) {
                int r = r0 + rr * 8;
                float A0 = 100.f * (d[rr * 2] + bv0);
                float A1 = 100.f * (d[rr * 2 + 1] + bv1);
                float e0 = __expf(-fabsf(A0)), e1 = __expf(-fabsf(A1));
                float sp0 = (fmaxf(A0, 0.f) + __logf(1.f + e0)) * 0.01f;
                float sp1 = (fmaxf(A1, 0.f) + __logf(1.f + e1)) * 0.01f;
                float i0 = __fdividef(1.f, 1.f + e0);
                float i1 = __fdividef(1.f, 1.f + e1);
                float sg0 = (A0 >= 0.f) ? i0 : e0 * i0;
                float sg1 = (A1 >= 0.f) ? i1 : e1 * i1;
                __half h0, l0, h1, l1;
                split2h(sp0, h0, l0);
                split2h(sp1, h1, l1);
                __half* yh = Yhi + (size_t)r * PITCH;
                __half* yl = Ylo + (size_t)r * PITCH;
                float* gp = g_gate + (size_t)r * PITCH;
                if (cg + 1 < cout) {
                    *(uint32_t*)(yh + cg) = (uint32_t)__half_as_ushort(h0)
                                          | ((uint32_t)__half_as_ushort(h1) << 16);
                    *(uint32_t*)(yl + cg) = (uint32_t)__half_as_ushort(l0)
                                          | ((uint32_t)__half_as_ushort(l1) << 16);
                    *(float2*)(gp + cg) = make_float2(sg0, sg1);
                } else if (cg < cout) {
                    yh[cg] = h0;
                    yl[cg] = l0;
                    gp[cg] = sg0;
                }
            }
        }
    }
}

// ===========================================================================
// g-layer kernel: 2-term GEMM (Whi+Wlo)*ghi on 49152 gradient rows.
// ===========================================================================
#define GA  0
#define GBH 8192
#define GBL 16384
#define STG_G 24576
#define SMEM_G (STAGES * STG_G)

__global__ void __launch_bounds__(256, 2)
layer_g_kernel(int cin, int cout, int wpitch, size_t woff, int flip)
{
    extern __shared__ char smem[];
    const uint32_t sb = smem_u32(smem);
    const int t = threadIdx.x;
    const int lane = t & 31, wid = t >> 5;

    const __half* __restrict__ G = flip ? g_ghiB : g_ghiA;
    __half* __restrict__ Y = flip ? g_ghiA : g_ghiB;
    const __half* __restrict__ Wh = g_Whi + woff;
    const __half* __restrict__ Wl = g_Wlo + woff;

    const int cblk = blockIdx.x * 128;
    const int nblk = blockIdx.y * 128;

    const int ktiles = (cin + 31) >> 5;

    auto load_stage = [&](int s, int kt) {
        const uint32_t base = sb + (uint32_t)s * STG_G;
        const int k0 = kt << 5;
        #pragma unroll
        for (int i = 0; i < 2; i++) {               // A (ghi): 512 granules
            int li = t + (i << 8);
            int r = li >> 2, g = li & 3;
            int kk = k0 + g * 8, rem = cin - kk;
            int sz = rem >= 8 ? 16 : (rem > 0 ? rem * 2 : 0);
            uint32_t o = SWZ64((uint32_t)(r * 64 + g * 16));
            cpa16(base + GA + o, G + (size_t)(nblk + r) * PITCH + kk, sz);
        }
        #pragma unroll
        for (int i = 0; i < 2; i++) {               // B hi/lo: 512 granules x2
            int li = t + (i << 8);
            int r = li >> 2, g = li & 3;
            int row = cblk + r;
            int kk = k0 + g * 8, rem = cin - kk;
            int sz = (row < cout) ? (rem >= 8 ? 16 : (rem > 0 ? rem * 2 : 0)) : 0;
            uint32_t o = SWZ64((uint32_t)(r * 64 + g * 16));
            const size_t so = (size_t)row * wpitch + kk;
            cpa16(base + GBH + o, Wh + so, sz);
            cpa16(base + GBL + o, Wl + so, sz);
        }
        cpa_commit();
    };

    const int wm = wid >> 2, wn = wid & 3;
    const int seg = lane >> 3, i7 = lane & 7;
    uint32_t aR[4], aX[4];
    #pragma unroll
    for (int mi = 0; mi < 4; mi++) {
        int r = wm * 64 + mi * 16 + (seg & 1) * 8 + i7;
        aR[mi] = (uint32_t)(r * 64);
        aX[mi] = (aR[mi] >> 3) & 0x30;
    }
    const uint32_t akd = (uint32_t)((seg >> 1) * 16);
    uint32_t bR[2], bX[2];
    #pragma unroll
    for (int np = 0; np < 2; np++) {
        int r = wn * 32 + np * 16 + (seg >> 1) * 8 + i7;
        bR[np] = (uint32_t)(r * 64);
        bX[np] = (bR[np] >> 3) & 0x30;
    }
    const uint32_t bkd = (uint32_t)((seg & 1) * 16);

    float acc[4][4][4];
    #pragma unroll
    for (int mi = 0; mi < 4; mi++)
        #pragma unroll
        for (int ni = 0; ni < 4; ni++)
            #pragma unroll
            for (int r = 0; r < 4; r++) acc[mi][ni][r] = 0.f;

    auto compute = [&](int s) {
        const uint32_t base = sb + (uint32_t)s * STG_G;
        #pragma unroll
        for (int st = 0; st < 2; st++) {
            const uint32_t kb = (uint32_t)(st * 32);
            uint32_t Ah[4][4], Bh[2][4];
            #pragma unroll
            for (int mi = 0; mi < 4; mi++)
                ldsm4(Ah[mi], base + GA + aR[mi] + ((kb + akd) ^ aX[mi]));
            #pragma unroll
            for (int np = 0; np < 2; np++)
                ldsm4(Bh[np], base + GBH + bR[np] + ((kb + bkd) ^ bX[np]));
            #pragma unroll
            for (int mi = 0; mi < 4; mi++)
                #pragma unroll
                for (int ni = 0; ni < 4; ni++)
                    mma_f16(acc[mi][ni], Ah[mi],
                            Bh[ni >> 1][(ni & 1) * 2], Bh[ni >> 1][(ni & 1) * 2 + 1]);
            {
                uint32_t Bl[2][4];
                #pragma unroll
                for (int np = 0; np < 2; np++)
                    ldsm4(Bl[np], base + GBL + bR[np] + ((kb + bkd) ^ bX[np]));
                #pragma unroll
                for (int mi = 0; mi < 4; mi++)
                    #pragma unroll
                    for (int ni = 0; ni < 4; ni++)
                        mma_f16(acc[mi][ni], Ah[mi],
                                Bl[ni >> 1][(ni & 1) * 2], Bl[ni >> 1][(ni & 1) * 2 + 1]);
            }
        }
    };

    load_stage(0, 0);
    if (ktiles > 1) load_stage(1, 1); else cpa_commit();
    for (int kt = 0; kt < ktiles; kt++) {
        asm volatile("cp.async.wait_group 1;" ::: "memory");
        __syncthreads();
        int nf = kt + 2;
        if (nf < ktiles) load_stage(nf % STAGES, nf); else cpa_commit();
        compute(kt % STAGES);
    }

    // epilogue: g' = gate[p][c] * D; write ghi (single fp16)
    const int q = lane >> 2, c2 = (lane & 3) * 2;
    #pragma unroll
    for (int mi = 0; mi < 4; mi++) {
        int r0 = nblk + wm * 64 + mi * 16 + q;
        #pragma unroll
        for (int rr = 0; rr < 2; rr++) {
            int r = r0 + rr * 8;
            int p = r / 3;
            const float* gp = g_gate + (size_t)p * PITCH;
            __half* yr = Y + (size_t)r * PITCH;
            #pragma unroll
            for (int ni = 0; ni < 4; ni++) {
                int cg = cblk + wn * 32 + ni * 8 + c2;
                float d0 = acc[mi][ni][rr * 2], d1 = acc[mi][ni][rr * 2 + 1];
                if (cg + 1 < cout) {
                    float2 sg = *(const float2*)(gp + cg);
                    __half h0 = __float2half_rn(sg.x * d0);
                    __half h1 = __float2half_rn(sg.y * d1);
                    *(uint32_t*)(yr + cg) = (uint32_t)__half_as_ushort(h0)
                                          | ((uint32_t)__half_as_ushort(h1) << 16);
                } else if (cg < cout) {
                    yr[cg] = __float2half_rn(gp[cg] * d0);
                }
            }
        }
    }
}

// ---- final layer: cout=1; z from x-state, g from g-state ------------------
__global__ void final_kernel(const float* __restrict__ W,
                             const float* __restrict__ bias,
                             float* __restrict__ out)
{
    int gw = (blockIdx.x * blockDim.x + threadIdx.x) >> 5;
    int lane = threadIdx.x & 31;
    if (gw >= NPTS + NGR) return;
    float s = 0.f;
    if (gw < NPTS) {                        // z row: x-state hi+lo
        const __half* hp = g_xhiB + (size_t)gw * PITCH;
        const __half* lp = g_xloB + (size_t)gw * PITCH;
        for (int i = lane; i < 112; i += 32) {
            uint4 hv = *(const uint4*)(hp + i * 8);
            uint4 lv = *(const uint4*)(lp + i * 8);
            float4 w0 = __ldg((const float4*)W + i * 2);
            float4 w1 = __ldg((const float4*)W + i * 2 + 1);
            const uint32_t* hw = &hv.x;
            const uint32_t* lw = &lv.x;
            float wf2[8] = {w0.x, w0.y, w0.z, w0.w, w1.x, w1.y, w1.z, w1.w};
            #pragma unroll
            for (int qq = 0; qq < 4; qq++) {
                float2 fh = __half22float2(*(const __half2*)&hw[qq]);
                float2 fl = __half22float2(*(const __half2*)&lw[qq]);
                s = fmaf(wf2[2 * qq],     fh.x + fl.x, s);
                s = fmaf(wf2[2 * qq + 1], fh.y + fl.y, s);
            }
        }
        #pragma unroll
        for (int o = 16; o; o >>= 1) s += __shfl_xor_sync(0xffffffffu, s, o);
        if (lane == 0) out[gw] = s + bias[0];
    } else {                                // gradient row: ghi only
        int r = gw - NPTS;
        const __half* hp = g_ghiB + (size_t)r * PITCH;
        for (int i = lane; i < 112; i += 32) {
            uint4 hv = *(const uint4*)(hp + i * 8);
            float4 w0 = __ldg((const float4*)W + i * 2);
            float4 w1 = __ldg((const float4*)W + i * 2 + 1);
            const uint32_t* hw = &hv.x;
            float wf2[8] = {w0.x, w0.y, w0.z, w0.w, w1.x, w1.y, w1.z, w1.w};
            #pragma unroll
            for (int qq = 0; qq < 4; qq++) {
                float2 fh = __half22float2(*(const __half2*)&hw[qq]);
                s = fmaf(wf2[2 * qq],     fh.x, s);
                s = fmaf(wf2[2 * qq + 1], fh.y, s);
            }
        }
        #pragma unroll
        for (int o = 16; o; o >>= 1) s += __shfl_xor_sync(0xffffffffu, s, o);
        if (lane == 0) out[NPTS + r] = s;   // r = 3p+ci maps directly
    }
}

// ---------------------------------------------------------------------------
extern "C" void kernel_launch(void* const* d_in, const int* in_sizes, int n_in,
                              void* d_out, int out_size)
{
    const float* input  = (const float*)d_in[0];
    const float* latent = (const float*)d_in[1];
    float* out = (float*)d_out;
    float* out_con = out + NPTS + NPTS * 3;

    {
        WPtrs wp;
        for (int l = 0; l < 11; l++) wp.w[l] = (const float*)d_in[2 + 2 * l];
        dim3 grid((960 * 960 + 255) / 256, 11);
        prep_all_kernel<<<grid, 256>>>(wp);
    }
    {
        int tot = NPTS * 259;
        init_kernel<<<(tot + 255) / 256, 256>>>(input, latent, out_con);
    }

    cudaFuncSetAttribute(layer_x_kernel,
                         cudaFuncAttributeMaxDynamicSharedMemorySize, SMEM_X);
    cudaFuncSetAttribute(layer_g_kernel,
                         cudaFuncAttributeMaxDynamicSharedMemorySize, SMEM_G);

    for (int l = 0; l < 11; l++) {
        const float* b = (const float*)d_in[3 + 2 * l];
        dim3 gx((LCOUT[l] + 127) / 128, NPTS / 128);
        layer_x_kernel<<<gx, 256, SMEM_X>>>(b, LCIN[l], LCOUT[l],
                                            LPIT[l], LWOFF[l], l & 1);
        dim3 gg((LCOUT[l] + 127) / 128, NGR / 128);
        layer_g_kernel<<<gg, 256, SMEM_G>>>(LCIN[l], LCOUT[l],
                                            LPIT[l], LWOFF[l], l & 1);
    }

    final_kernel<<<(NPTS + NGR) * 32 / 256, 256>>>((const float*)d_in[24],
                                                   (const float*)d_in[25], out);
}

// round 13
// speedup vs baseline: 1.8679x; 1.0470x over previous
#include <cuda_runtime.h>
#include <cuda_fp16.h>
#include <math.h>
#include <stdint.h>

// ===========================================================================
// ImplicitMap_fExtrator — Round 13: r12 merged-launch design with the gate
// parity bug fixed (g_body now reads the SAME buffer x_body writes for a
// given layer parity: flip ? gateA : gateB).
// Structure: K_l = {x-layer l+1, g-layer l} in ONE launch, Bresenham-
// interleaved CTAs; gate double-buffered (parity l&1) so the concurrent
// x_{l+1} write (parity (l+1)&1) never collides with the g_l read.
// ===========================================================================

#define NPTS   16384
#define NGR    49152          // 3 * NPTS gradient rows
#define PITCH  960

__device__ __half g_xhiA[(size_t)NPTS * PITCH];
__device__ __half g_xloA[(size_t)NPTS * PITCH];
__device__ __half g_xhiB[(size_t)NPTS * PITCH];
__device__ __half g_xloB[(size_t)NPTS * PITCH];
__device__ __half g_ghiA[(size_t)NGR * PITCH];
__device__ __half g_ghiB[(size_t)NGR * PITCH];
__device__ float  g_gateA[(size_t)NPTS * PITCH];
__device__ float  g_gateB[(size_t)NPTS * PITCH];
__device__ __half g_Whi[5600000];
__device__ __half g_Wlo[5600000];

static const int    LCIN [11] = {259,515,512,512,576,576,768,768,768,960,960};
static const int    LCOUT[11] = {515,512,512,576,576,768,768,768,960,960,896};
static const int    LPIT [11] = {264,520,512,512,576,576,768,768,768,960,960};
static const size_t LWOFF[11] = {0,135960,402200,664344,959256,1291032,1733400,
                                 2323224,2913048,3650328,4571928};

__device__ const int    d_LCIN [11] = {259,515,512,512,576,576,768,768,768,960,960};
__device__ const int    d_LCOUT[11] = {515,512,512,576,576,768,768,768,960,960,896};
__device__ const int    d_LPIT [11] = {264,520,512,512,576,576,768,768,768,960,960};
__device__ const size_t d_LWOFF[11] = {0,135960,402200,664344,959256,1291032,1733400,
                                       2323224,2913048,3650328,4571928};

// ---- PTX helpers ----------------------------------------------------------
__device__ __forceinline__ uint32_t smem_u32(const void* p) {
    uint32_t a;
    asm("{ .reg .u64 t; cvta.to.shared.u64 t, %1; cvt.u32.u64 %0, t; }"
        : "=r"(a) : "l"(p));
    return a;
}
__device__ __forceinline__ void cpa16(uint32_t dst, const void* src, int sz) {
    asm volatile("cp.async.cg.shared.global [%0], [%1], 16, %2;"
                 :: "r"(dst), "l"(src), "r"(sz));
}
__device__ __forceinline__ void cpa_commit() {
    asm volatile("cp.async.commit_group;" ::: "memory");
}
__device__ __forceinline__ void ldsm4(uint32_t* r, uint32_t a) {
    asm volatile("ldmatrix.sync.aligned.m8n8.x4.shared.b16 {%0,%1,%2,%3}, [%4];"
                 : "=r"(r[0]), "=r"(r[1]), "=r"(r[2]), "=r"(r[3]) : "r"(a));
}
__device__ __forceinline__ void mma_f16(float* d, const uint32_t* a,
                                        uint32_t b0, uint32_t b1) {
    asm volatile("mma.sync.aligned.m16n8k16.row.col.f32.f16.f16.f32 "
                 "{%0,%1,%2,%3}, {%4,%5,%6,%7}, {%8,%9}, {%0,%1,%2,%3};"
                 : "+f"(d[0]), "+f"(d[1]), "+f"(d[2]), "+f"(d[3])
                 : "r"(a[0]), "r"(a[1]), "r"(a[2]), "r"(a[3]),
                   "r"(b0), "r"(b1));
}
__device__ __forceinline__ void split2h(float v, __half& h, __half& l) {
    h = __float2half_rn(v);
    l = __float2half_rn(v - __half2float(h));
}

// ---- fused W prep ----------------------------------------------------------
struct WPtrs { const float* w[11]; };

__global__ void prep_all_kernel(WPtrs wp)
{
    int l = blockIdx.y;
    int idx = blockIdx.x * blockDim.x + threadIdx.x;
    int cin = d_LCIN[l];
    int cnt = cin * d_LCOUT[l];
    if (idx >= cnt) return;
    int row = idx / cin, col = idx - row * cin;
    __half h, lo;
    split2h(wp.w[l][idx], h, lo);
    size_t d = d_LWOFF[l] + (size_t)row * d_LPIT[l] + col;
    g_Whi[d] = h;
    g_Wlo[d] = lo;
}

// ---- init ------------------------------------------------------------------
__global__ void init_kernel(const float* __restrict__ inp,
                            const float* __restrict__ lat,
                            float* __restrict__ out_con)
{
    int idx = blockIdx.x * blockDim.x + threadIdx.x;   // NPTS*259
    if (idx >= NPTS * 259) return;
    int p = idx / 259;
    int c = idx - p * 259;
    int b = p >> 13;
    float v = (c < 3) ? inp[p * 3 + c] : lat[b * 256 + (c - 3)];
    out_con[idx] = v;
    __half h, l;
    split2h(v, h, l);
    size_t xo = (size_t)p * PITCH + c;
    g_xhiA[xo] = h;
    g_xloA[xo] = l;
    #pragma unroll
    for (int ci = 0; ci < 3; ci++) {
        g_ghiA[(size_t)(3 * p + ci) * PITCH + c] =
            __float2half_rn((c == ci) ? 1.0f : 0.0f);
    }
}

// ---- tile/layout constants -------------------------------------------------
#define STAGES 3
#define XAHI 0
#define XALO 8192
#define XBHI 16384
#define XBLO 24576
#define STG_X 32768
#define SMEM_X (STAGES * STG_X)
#define GA  0
#define GBH 8192
#define GBL 16384
#define STG_G 24576
#define SMEM_CB SMEM_X
#define SWZ64(o) ((o) ^ (((o) >> 3) & 0x30))

// ===========================================================================
// x body: 3-term split GEMM + softplus/sigma epilogue (writes gate[flip])
// ===========================================================================
__device__ __forceinline__ void x_body(
    char* smem, float* bias_s, const float* __restrict__ bias,
    int cin, int cout, int wpitch, size_t woff, int flip,
    int cblk, int nblk, int t)
{
    const uint32_t sb = smem_u32(smem);
    const int lane = t & 31, wid = t >> 5;

    const __half* __restrict__ Xhi = flip ? g_xhiB : g_xhiA;
    const __half* __restrict__ Xlo = flip ? g_xloB : g_xloA;
    __half* __restrict__ Yhi = flip ? g_xhiA : g_xhiB;
    __half* __restrict__ Ylo = flip ? g_xloA : g_xloB;
    float* __restrict__ gate_wr = flip ? g_gateA : g_gateB;  // gate[L&1]
    const __half* __restrict__ Wh = g_Whi + woff;
    const __half* __restrict__ Wl = g_Wlo + woff;

    if (t < 128) {
        int c = cblk + t;
        bias_s[t] = (c < cout) ? __ldg(bias + c) : 0.f;
    }

    const int ktiles = (cin + 31) >> 5;

    auto load_stage = [&](int s, int kt) {
        const uint32_t base = sb + (uint32_t)s * STG_X;
        const int k0 = kt << 5;
        #pragma unroll
        for (int i = 0; i < 2; i++) {
            int li = t + (i << 8);
            int r = li >> 2, g = li & 3;
            int kk = k0 + g * 8, rem = cin - kk;
            int sz = rem >= 8 ? 16 : (rem > 0 ? rem * 2 : 0);
            uint32_t o = SWZ64((uint32_t)(r * 64 + g * 16));
            const size_t so = (size_t)(nblk + r) * PITCH + kk;
            cpa16(base + XAHI + o, Xhi + so, sz);
            cpa16(base + XALO + o, Xlo + so, sz);
        }
        #pragma unroll
        for (int i = 0; i < 2; i++) {
            int li = t + (i << 8);
            int r = li >> 2, g = li & 3;
            int row = cblk + r;
            int kk = k0 + g * 8, rem = cin - kk;
            int sz = (row < cout) ? (rem >= 8 ? 16 : (rem > 0 ? rem * 2 : 0)) : 0;
            uint32_t o = SWZ64((uint32_t)(r * 64 + g * 16));
            const size_t so = (size_t)row * wpitch + kk;
            cpa16(base + XBHI + o, Wh + so, sz);
            cpa16(base + XBLO + o, Wl + so, sz);
        }
        cpa_commit();
    };

    const int wm = wid >> 2, wn = wid & 3;
    const int seg = lane >> 3, i7 = lane & 7;
    uint32_t aR[4], aX[4];
    #pragma unroll
    for (int mi = 0; mi < 4; mi++) {
        int r = wm * 64 + mi * 16 + (seg & 1) * 8 + i7;
        aR[mi] = (uint32_t)(r * 64);
        aX[mi] = (aR[mi] >> 3) & 0x30;
    }
    const uint32_t akd = (uint32_t)((seg >> 1) * 16);
    uint32_t bR[2], bX[2];
    #pragma unroll
    for (int np = 0; np < 2; np++) {
        int r = wn * 32 + np * 16 + (seg >> 1) * 8 + i7;
        bR[np] = (uint32_t)(r * 64);
        bX[np] = (bR[np] >> 3) & 0x30;
    }
    const uint32_t bkd = (uint32_t)((seg & 1) * 16);

    float acc[4][4][4];
    #pragma unroll
    for (int mi = 0; mi < 4; mi++)
        #pragma unroll
        for (int ni = 0; ni < 4; ni++)
            #pragma unroll
            for (int r = 0; r < 4; r++) acc[mi][ni][r] = 0.f;

    auto compute = [&](int s) {
        const uint32_t base = sb + (uint32_t)s * STG_X;
        #pragma unroll
        for (int st = 0; st < 2; st++) {
            const uint32_t kb = (uint32_t)(st * 32);
            uint32_t Ah[4][4], Bh[2][4];
            #pragma unroll
            for (int mi = 0; mi < 4; mi++)
                ldsm4(Ah[mi], base + XAHI + aR[mi] + ((kb + akd) ^ aX[mi]));
            #pragma unroll
            for (int np = 0; np < 2; np++)
                ldsm4(Bh[np], base + XBHI + bR[np] + ((kb + bkd) ^ bX[np]));
            #pragma unroll
            for (int mi = 0; mi < 4; mi++)
                #pragma unroll
                for (int ni = 0; ni < 4; ni++)
                    mma_f16(acc[mi][ni], Ah[mi],
                            Bh[ni >> 1][(ni & 1) * 2], Bh[ni >> 1][(ni & 1) * 2 + 1]);
            {
                uint32_t Al[4][4];
                #pragma unroll
                for (int mi = 0; mi < 4; mi++)
                    ldsm4(Al[mi], base + XALO + aR[mi] + ((kb + akd) ^ aX[mi]));
                #pragma unroll
                for (int mi = 0; mi < 4; mi++)
                    #pragma unroll
                    for (int ni = 0; ni < 4; ni++)
                        mma_f16(acc[mi][ni], Al[mi],
                                Bh[ni >> 1][(ni & 1) * 2], Bh[ni >> 1][(ni & 1) * 2 + 1]);
            }
            {
                uint32_t Bl[2][4];
                #pragma unroll
                for (int np = 0; np < 2; np++)
                    ldsm4(Bl[np], base + XBLO + bR[np] + ((kb + bkd) ^ bX[np]));
                #pragma unroll
                for (int mi = 0; mi < 4; mi++)
                    #pragma unroll
                    for (int ni = 0; ni < 4; ni++)
                        mma_f16(acc[mi][ni], Ah[mi],
                                Bl[ni >> 1][(ni & 1) * 2], Bl[ni >> 1][(ni & 1) * 2 + 1]);
            }
        }
    };

    load_stage(0, 0);
    if (ktiles > 1) load_stage(1, 1); else cpa_commit();
    for (int kt = 0; kt < ktiles; kt++) {
        asm volatile("cp.async.wait_group 1;" ::: "memory");
        __syncthreads();
        int nf = kt + 2;
        if (nf < ktiles) load_stage(nf % STAGES, nf); else cpa_commit();
        compute(kt % STAGES);
    }

    const int q = lane >> 2, c2 = (lane & 3) * 2;
    #pragma unroll
    for (int mi = 0; mi < 4; mi++) {
        int r0 = nblk + wm * 64 + mi * 16 + q;
        #pragma unroll
        for (int ni = 0; ni < 4; ni++) {
            int nloc = wn * 32 + ni * 8 + c2;
            int cg = cblk + nloc;
            float bv0 = bias_s[nloc], bv1 = bias_s[nloc + 1];
            const float* d = acc[mi][ni];
            #pragma unroll
            for (int rr = 0; rr < 2; rr++) {
                int r = r0 + rr * 8;
                float A0 = 100.f * (d[rr * 2] + bv0);
                float A1 = 100.f * (d[rr * 2 + 1] + bv1);
                float e0 = __expf(-fabsf(A0)), e1 = __expf(-fabsf(A1));
                float sp0 = (fmaxf(A0, 0.f) + __logf(1.f + e0)) * 0.01f;
                float sp1 = (fmaxf(A1, 0.f) + __logf(1.f + e1)) * 0.01f;
                float i0 = __fdividef(1.f, 1.f + e0);
                float i1 = __fdividef(1.f, 1.f + e1);
                float sg0 = (A0 >= 0.f) ? i0 : e0 * i0;
                float sg1 = (A1 >= 0.f) ? i1 : e1 * i1;
                __half h0, l0, h1, l1;
                split2h(sp0, h0, l0);
                split2h(sp1, h1, l1);
                __half* yh = Yhi + (size_t)r * PITCH;
                __half* yl = Ylo + (size_t)r * PITCH;
                float* gp = gate_wr + (size_t)r * PITCH;
                if (cg + 1 < cout) {
                    *(uint32_t*)(yh + cg) = (uint32_t)__half_as_ushort(h0)
                                          | ((uint32_t)__half_as_ushort(h1) << 16);
                    *(uint32_t*)(yl + cg) = (uint32_t)__half_as_ushort(l0)
                                          | ((uint32_t)__half_as_ushort(l1) << 16);
                    *(float2*)(gp + cg) = make_float2(sg0, sg1);
                } else if (cg < cout) {
                    yh[cg] = h0;
                    yl[cg] = l0;
                    gp[cg] = sg0;
                }
            }
        }
    }
}

// ===========================================================================
// g body: 2-term GEMM (Whi+Wlo)*ghi + gate multiply (reads gate[flip])
// ===========================================================================
__device__ __forceinline__ void g_body(
    char* smem, int cin, int cout, int wpitch, size_t woff, int flip,
    int cblk, int nblk, int t)
{
    const uint32_t sb = smem_u32(smem);
    const int lane = t & 31, wid = t >> 5;

    const __half* __restrict__ G = flip ? g_ghiB : g_ghiA;
    __half* __restrict__ Y = flip ? g_ghiA : g_ghiB;
    // FIX (r12 bug): must read the SAME buffer x_body writes for this layer
    // parity: gate[l&1] = flip ? g_gateA : g_gateB.
    const float* __restrict__ gate_rd = flip ? g_gateA : g_gateB;
    const __half* __restrict__ Wh = g_Whi + woff;
    const __half* __restrict__ Wl = g_Wlo + woff;

    const int ktiles = (cin + 31) >> 5;

    auto load_stage = [&](int s, int kt) {
        const uint32_t base = sb + (uint32_t)s * STG_G;
        const int k0 = kt << 5;
        #pragma unroll
        for (int i = 0; i < 2; i++) {
            int li = t + (i << 8);
            int r = li >> 2, g = li & 3;
            int kk = k0 + g * 8, rem = cin - kk;
            int sz = rem >= 8 ? 16 : (rem > 0 ? rem * 2 : 0);
            uint32_t o = SWZ64((uint32_t)(r * 64 + g * 16));
            cpa16(base + GA + o, G + (size_t)(nblk + r) * PITCH + kk, sz);
        }
        #pragma unroll
        for (int i = 0; i < 2; i++) {
            int li = t + (i << 8);
            int r = li >> 2, g = li & 3;
            int row = cblk + r;
            int kk = k0 + g * 8, rem = cin - kk;
            int sz = (row < cout) ? (rem >= 8 ? 16 : (rem > 0 ? rem * 2 : 0)) : 0;
            uint32_t o = SWZ64((uint32_t)(r * 64 + g * 16));
            const size_t so = (size_t)row * wpitch + kk;
            cpa16(base + GBH + o, Wh + so, sz);
            cpa16(base + GBL + o, Wl + so, sz);
        }
        cpa_commit();
    };

    const int wm = wid >> 2, wn = wid & 3;
    const int seg = lane >> 3, i7 = lane & 7;
    uint32_t aR[4], aX[4];
    #pragma unroll
    for (int mi = 0; mi < 4; mi++) {
        int r = wm * 64 + mi * 16 + (seg & 1) * 8 + i7;
        aR[mi] = (uint32_t)(r * 64);
        aX[mi] = (aR[mi] >> 3) & 0x30;
    }
    const uint32_t akd = (uint32_t)((seg >> 1) * 16);
    uint32_t bR[2], bX[2];
    #pragma unroll
    for (int np = 0; np < 2; np++) {
        int r = wn * 32 + np * 16 + (seg >> 1) * 8 + i7;
        bR[np] = (uint32_t)(r * 64);
        bX[np] = (bR[np] >> 3) & 0x30;
    }
    const uint32_t bkd = (uint32_t)((seg & 1) * 16);

    float acc[4][4][4];
    #pragma unroll
    for (int mi = 0; mi < 4; mi++)
        #pragma unroll
        for (int ni = 0; ni < 4; ni++)
            #pragma unroll
            for (int r = 0; r < 4; r++) acc[mi][ni][r] = 0.f;

    auto compute = [&](int s) {
        const uint32_t base = sb + (uint32_t)s * STG_G;
        #pragma unroll
        for (int st = 0; st < 2; st++) {
            const uint32_t kb = (uint32_t)(st * 32);
            uint32_t Ah[4][4], Bh[2][4];
            #pragma unroll
            for (int mi = 0; mi < 4; mi++)
                ldsm4(Ah[mi], base + GA + aR[mi] + ((kb + akd) ^ aX[mi]));
            #pragma unroll
            for (int np = 0; np < 2; np++)
                ldsm4(Bh[np], base + GBH + bR[np] + ((kb + bkd) ^ bX[np]));
            #pragma unroll
            for (int mi = 0; mi < 4; mi++)
                #pragma unroll
                for (int ni = 0; ni < 4; ni++)
                    mma_f16(acc[mi][ni], Ah[mi],
                            Bh[ni >> 1][(ni & 1) * 2], Bh[ni >> 1][(ni & 1) * 2 + 1]);
            {
                uint32_t Bl[2][4];
                #pragma unroll
                for (int np = 0; np < 2; np++)
                    ldsm4(Bl[np], base + GBL + bR[np] + ((kb + bkd) ^ bX[np]));
                #pragma unroll
                for (int mi = 0; mi < 4; mi++)
                    #pragma unroll
                    for (int ni = 0; ni < 4; ni++)
                        mma_f16(acc[mi][ni], Ah[mi],
                                Bl[ni >> 1][(ni & 1) * 2], Bl[ni >> 1][(ni & 1) * 2 + 1]);
            }
        }
    };

    load_stage(0, 0);
    if (ktiles > 1) load_stage(1, 1); else cpa_commit();
    for (int kt = 0; kt < ktiles; kt++) {
        asm volatile("cp.async.wait_group 1;" ::: "memory");
        __syncthreads();
        int nf = kt + 2;
        if (nf < ktiles) load_stage(nf % STAGES, nf); else cpa_commit();
        compute(kt % STAGES);
    }

    const int q = lane >> 2, c2 = (lane & 3) * 2;
    #pragma unroll
    for (int mi = 0; mi < 4; mi++) {
        int r0 = nblk + wm * 64 + mi * 16 + q;
        #pragma unroll
        for (int rr = 0; rr < 2; rr++) {
            int r = r0 + rr * 8;
            int p = r / 3;
            const float* gp = gate_rd + (size_t)p * PITCH;
            __half* yr = Y + (size_t)r * PITCH;
            #pragma unroll
            for (int ni = 0; ni < 4; ni++) {
                int cg = cblk + wn * 32 + ni * 8 + c2;
                float d0 = acc[mi][ni][rr * 2], d1 = acc[mi][ni][rr * 2 + 1];
                if (cg + 1 < cout) {
                    float2 sg = *(const float2*)(gp + cg);
                    __half h0 = __float2half_rn(sg.x * d0);
                    __half h1 = __float2half_rn(sg.y * d1);
                    *(uint32_t*)(yr + cg) = (uint32_t)__half_as_ushort(h0)
                                          | ((uint32_t)__half_as_ushort(h1) << 16);
                } else if (cg < cout) {
                    yr[cg] = __float2half_rn(gp[cg] * d0);
                }
            }
        }
    }
}

// ===========================================================================
// combined kernel: Bresenham-interleaved x-CTAs (nx) and g-CTAs (rest)
// ===========================================================================
__global__ void __launch_bounds__(256, 2)
combined_kernel(const float* __restrict__ bias,
                int cinx, int coutx, int wpitx, size_t woffx, int flipx, int nctx,
                int cing, int coutg, int wpitg, size_t woffg, int flipg, int nctg,
                int nx)
{
    extern __shared__ char smem[];
    __shared__ float bias_s[128];
    const int b = blockIdx.x;
    const int T = gridDim.x;
    const int t = threadIdx.x;

    uint64_t pr = (uint64_t)b * (uint32_t)nx;
    bool is_x = (pr % (uint32_t)T) >= (uint64_t)(T - nx);
    if (is_x) {
        int xi = (int)(pr / (uint32_t)T);
        int cblk = (xi % nctx) * 128;
        int nblk = (xi / nctx) * 128;
        x_body(smem, bias_s, bias, cinx, coutx, wpitx, woffx, flipx,
               cblk, nblk, t);
    } else {
        int gi = b - (int)(((uint64_t)(b + 1) * (uint32_t)nx) / (uint32_t)T);
        int cblk = (gi % nctg) * 128;
        int nblk = (gi / nctg) * 128;
        g_body(smem, cing, coutg, wpitg, woffg, flipg, cblk, nblk, t);
    }
}

// ---- final layer: cout=1; z from x-state, g from g-state ------------------
__global__ void final_kernel(const float* __restrict__ W,
                             const float* __restrict__ bias,
                             float* __restrict__ out)
{
    int gw = (blockIdx.x * blockDim.x + threadIdx.x) >> 5;
    int lane = threadIdx.x & 31;
    if (gw >= NPTS + NGR) return;
    float s = 0.f;
    if (gw < NPTS) {
        const __half* hp = g_xhiB + (size_t)gw * PITCH;
        const __half* lp = g_xloB + (size_t)gw * PITCH;
        for (int i = lane; i < 112; i += 32) {
            uint4 hv = *(const uint4*)(hp + i * 8);
            uint4 lv = *(const uint4*)(lp + i * 8);
            float4 w0 = __ldg((const float4*)W + i * 2);
            float4 w1 = __ldg((const float4*)W + i * 2 + 1);
            const uint32_t* hw = &hv.x;
            const uint32_t* lw = &lv.x;
            float wf2[8] = {w0.x, w0.y, w0.z, w0.w, w1.x, w1.y, w1.z, w1.w};
            #pragma unroll
            for (int qq = 0; qq < 4; qq++) {
                float2 fh = __half22float2(*(const __half2*)&hw[qq]);
                float2 fl = __half22float2(*(const __half2*)&lw[qq]);
                s = fmaf(wf2[2 * qq],     fh.x + fl.x, s);
                s = fmaf(wf2[2 * qq + 1], fh.y + fl.y, s);
            }
        }
        #pragma unroll
        for (int o = 16; o; o >>= 1) s += __shfl_xor_sync(0xffffffffu, s, o);
        if (lane == 0) out[gw] = s + bias[0];
    } else {
        int r = gw - NPTS;
        const __half* hp = g_ghiB + (size_t)r * PITCH;
        for (int i = lane; i < 112; i += 32) {
            uint4 hv = *(const uint4*)(hp + i * 8);
            float4 w0 = __ldg((const float4*)W + i * 2);
            float4 w1 = __ldg((const float4*)W + i * 2 + 1);
            const uint32_t* hw = &hv.x;
            float wf2[8] = {w0.x, w0.y, w0.z, w0.w, w1.x, w1.y, w1.z, w1.w};
            #pragma unroll
            for (int qq = 0; qq < 4; qq++) {
                float2 fh = __half22float2(*(const __half2*)&hw[qq]);
                s = fmaf(wf2[2 * qq],     fh.x, s);
                s = fmaf(wf2[2 * qq + 1], fh.y, s);
            }
        }
        #pragma unroll
        for (int o = 16; o; o >>= 1) s += __shfl_xor_sync(0xffffffffu, s, o);
        if (lane == 0) out[NPTS + r] = s;
    }
}

// ---------------------------------------------------------------------------
extern "C" void kernel_launch(void* const* d_in, const int* in_sizes, int n_in,
                              void* d_out, int out_size)
{
    const float* input  = (const float*)d_in[0];
    const float* latent = (const float*)d_in[1];
    float* out = (float*)d_out;
    float* out_con = out + NPTS + NPTS * 3;

    {
        WPtrs wp;
        for (int l = 0; l < 11; l++) wp.w[l] = (const float*)d_in[2 + 2 * l];
        dim3 grid((960 * 960 + 255) / 256, 11);
        prep_all_kernel<<<grid, 256>>>(wp);
    }
    {
        int tot = NPTS * 259;
        init_kernel<<<(tot + 255) / 256, 256>>>(input, latent, out_con);
    }

    cudaFuncSetAttribute(combined_kernel,
                         cudaFuncAttributeMaxDynamicSharedMemorySize, SMEM_CB);

    // x-layer 0 alone
    {
        int nctx = (LCOUT[0] + 127) / 128;
        int nx = nctx * (NPTS / 128);
        combined_kernel<<<nx, 256, SMEM_CB>>>(
            (const float*)d_in[3],
            LCIN[0], LCOUT[0], LPIT[0], LWOFF[0], 0, nctx,
            0, 0, 0, 0, 0, 1, nx);
    }
    // K_l = x-layer l+1 + g-layer l, l = 0..9
    for (int l = 0; l < 10; l++) {
        int L = l + 1;
        int nctx = (LCOUT[L] + 127) / 128;
        int nx = nctx * (NPTS / 128);
        int nctg = (LCOUT[l] + 127) / 128;
        int ng = nctg * (NGR / 128);
        combined_kernel<<<nx + ng, 256, SMEM_CB>>>(
            (const float*)d_in[3 + 2 * L],
            LCIN[L], LCOUT[L], LPIT[L], LWOFF[L], L & 1, nctx,
            LCIN[l], LCOUT[l], LPIT[l], LWOFF[l], l & 1, nctg,
            nx);
    }
    // g-layer 10 alone
    {
        int nctg = (LCOUT[10] + 127) / 128;
        int ng = nctg * (NGR / 128);
        combined_kernel<<<ng, 256, SMEM_CB>>>(
            (const float*)d_in[3],
            0, 0, 0, 0, 0, 1,
            LCIN[10], LCOUT[10], LPIT[10], LWOFF[10], 10 & 1, nctg,
            0);
    }

    final_kernel<<<(NPTS + NGR) * 32 / 256, 256>>>((const float*)d_in[24],
                                                   (const float*)d_in[25], out);
}

// round 14
// speedup vs baseline: 2.6106x; 1.3977x over previous
#include <cuda_runtime.h>
#include <cuda_fp16.h>
#include <math.h>
#include <stdint.h>

// ===========================================================================
// ImplicitMap_fExtrator — Round 14: reverse-mode Jacobian.
// Output grad = W12·diag(s11)·W11·...·diag(s1)·W1[:,:3]  (1 row x 3 cols).
// Forward x-pass (3-term fp16 split, 16384 rows) stores ALL gates (fp32).
// Reverse pass propagates a single row u (hi/lo fp16, 3-term split) through
// transposed weights: u_{j-1} = (u_j · W_{j+1}) ⊙ gate_{j-1}.
// FLOPs: 3 (x) + 2.91 (reverse) = 5.9 units vs 9 units forward-mode (-35%).
// GEMM core = validated r7 config: Kc=32 x 3 stages, 64B XOR tiles, 256 thr,
// warp tile 64x32, 1 sync/iter, 2 CTAs/SM.
// ===========================================================================

#define NPTS   16384
#define PITCH  960

__device__ __half g_xhiA[(size_t)NPTS * PITCH];
__device__ __half g_xloA[(size_t)NPTS * PITCH];
__device__ __half g_xhiB[(size_t)NPTS * PITCH];
__device__ __half g_xloB[(size_t)NPTS * PITCH];
__device__ __half g_uhiA[(size_t)NPTS * PITCH];
__device__ __half g_uloA[(size_t)NPTS * PITCH];
__device__ __half g_uhiB[(size_t)NPTS * PITCH];
__device__ __half g_uloB[(size_t)NPTS * PITCH];
__device__ float  g_gate[(size_t)11 * NPTS * PITCH];     // all-layer gates
__device__ __half g_Whi [5600000];
__device__ __half g_Wlo [5600000];
__device__ __half g_Wthi[5600000];
__device__ __half g_Wtlo[5600000];

static const int    LCIN [11] = {259,515,512,512,576,576,768,768,768,960,960};
static const int    LCOUT[11] = {515,512,512,576,576,768,768,768,960,960,896};
static const int    LPIT [11] = {264,520,512,512,576,576,768,768,768,960,960};
static const size_t LWOFF[11] = {0,135960,402200,664344,959256,1291032,1733400,
                                 2323224,2913048,3650328,4571928};
static const int    WTPIT[11] = {520,512,512,576,576,768,768,768,960,960,896};
static const size_t WTOFF[11] = {0,134680,398360,660504,955416,1287192,1729560,
                                 2319384,2909208,3646488,4568088};

__device__ const int    d_LCIN [11] = {259,515,512,512,576,576,768,768,768,960,960};
__device__ const int    d_LCOUT[11] = {515,512,512,576,576,768,768,768,960,960,896};
__device__ const int    d_LPIT [11] = {264,520,512,512,576,576,768,768,768,960,960};
__device__ const size_t d_LWOFF[11] = {0,135960,402200,664344,959256,1291032,1733400,
                                       2323224,2913048,3650328,4571928};
__device__ const int    d_WTPIT[11] = {520,512,512,576,576,768,768,768,960,960,896};
__device__ const size_t d_WTOFF[11] = {0,134680,398360,660504,955416,1287192,1729560,
                                       2319384,2909208,3646488,4568088};

// ---- PTX helpers ----------------------------------------------------------
__device__ __forceinline__ uint32_t smem_u32(const void* p) {
    uint32_t a;
    asm("{ .reg .u64 t; cvta.to.shared.u64 t, %1; cvt.u32.u64 %0, t; }"
        : "=r"(a) : "l"(p));
    return a;
}
__device__ __forceinline__ void cpa16(uint32_t dst, const void* src, int sz) {
    asm volatile("cp.async.cg.shared.global [%0], [%1], 16, %2;"
                 :: "r"(dst), "l"(src), "r"(sz));
}
__device__ __forceinline__ void cpa_commit() {
    asm volatile("cp.async.commit_group;" ::: "memory");
}
__device__ __forceinline__ void ldsm4(uint32_t* r, uint32_t a) {
    asm volatile("ldmatrix.sync.aligned.m8n8.x4.shared.b16 {%0,%1,%2,%3}, [%4];"
                 : "=r"(r[0]), "=r"(r[1]), "=r"(r[2]), "=r"(r[3]) : "r"(a));
}
__device__ __forceinline__ void mma_f16(float* d, const uint32_t* a,
                                        uint32_t b0, uint32_t b1) {
    asm volatile("mma.sync.aligned.m16n8k16.row.col.f32.f16.f16.f32 "
                 "{%0,%1,%2,%3}, {%4,%5,%6,%7}, {%8,%9}, {%0,%1,%2,%3};"
                 : "+f"(d[0]), "+f"(d[1]), "+f"(d[2]), "+f"(d[3])
                 : "r"(a[0]), "r"(a[1]), "r"(a[2]), "r"(a[3]),
                   "r"(b0), "r"(b1));
}
__device__ __forceinline__ void split2h(float v, __half& h, __half& l) {
    h = __float2half_rn(v);
    l = __float2half_rn(v - __half2float(h));
}

// ---- fused W prep: forward (K-major cin) AND transposed (K-major cout) ----
struct WPtrs { const float* w[11]; };

__global__ void prep_all_kernel(WPtrs wp)
{
    int l = blockIdx.y;
    int idx = blockIdx.x * blockDim.x + threadIdx.x;
    int cin = d_LCIN[l];
    int cnt = cin * d_LCOUT[l];
    if (idx >= cnt) return;
    int row = idx / cin, col = idx - row * cin;
    __half h, lo;
    split2h(wp.w[l][idx], h, lo);
    size_t d = d_LWOFF[l] + (size_t)row * d_LPIT[l] + col;
    g_Whi[d] = h;
    g_Wlo[d] = lo;
    size_t dt = d_WTOFF[l] + (size_t)col * d_WTPIT[l] + row;
    g_Wthi[dt] = h;
    g_Wtlo[dt] = lo;
}

// ---- init ------------------------------------------------------------------
__global__ void init_kernel(const float* __restrict__ inp,
                            const float* __restrict__ lat,
                            float* __restrict__ out_con)
{
    int idx = blockIdx.x * blockDim.x + threadIdx.x;   // NPTS*259
    if (idx >= NPTS * 259) return;
    int p = idx / 259;
    int c = idx - p * 259;
    int b = p >> 13;
    float v = (c < 3) ? inp[p * 3 + c] : lat[b * 256 + (c - 3)];
    out_con[idx] = v;
    __half h, l;
    split2h(v, h, l);
    size_t xo = (size_t)p * PITCH + c;
    g_xhiA[xo] = h;
    g_xloA[xo] = l;
}

// ---- tile constants --------------------------------------------------------
#define STAGES 3
#define AHI 0
#define ALO 8192
#define BHI 16384
#define BLO 24576
#define STG_SZ 32768
#define SMEM_BYTES (STAGES * STG_SZ)
#define SWZ64(o) ((o) ^ (((o) >> 3) & 0x30))

// ===========================================================================
// x-layer: 3-term split GEMM + softplus epilogue; gate -> g_gate[goff]
// ===========================================================================
__global__ void __launch_bounds__(256, 2)
x_kernel(const float* __restrict__ bias, int cin, int cout,
         int wpitch, size_t woff, size_t goff, int flip)
{
    extern __shared__ char smem[];
    __shared__ float bias_s[128];
    const uint32_t sb = smem_u32(smem);
    const int t = threadIdx.x;
    const int lane = t & 31, wid = t >> 5;

    const __half* __restrict__ Xhi = flip ? g_xhiB : g_xhiA;
    const __half* __restrict__ Xlo = flip ? g_xloB : g_xloA;
    __half* __restrict__ Yhi = flip ? g_xhiA : g_xhiB;
    __half* __restrict__ Ylo = flip ? g_xloA : g_xloB;
    float* __restrict__ gate_wr = g_gate + goff;
    const __half* __restrict__ Wh = g_Whi + woff;
    const __half* __restrict__ Wl = g_Wlo + woff;

    const int cblk = blockIdx.x * 128;
    const int nblk = blockIdx.y * 128;

    if (t < 128) {
        int c = cblk + t;
        bias_s[t] = (c < cout) ? __ldg(bias + c) : 0.f;
    }

    const int ktiles = (cin + 31) >> 5;

    auto load_stage = [&](int s, int kt) {
        const uint32_t base = sb + (uint32_t)s * STG_SZ;
        const int k0 = kt << 5;
        #pragma unroll
        for (int i = 0; i < 2; i++) {
            int li = t + (i << 8);
            int r = li >> 2, g = li & 3;
            int kk = k0 + g * 8, rem = cin - kk;
            int sz = rem >= 8 ? 16 : (rem > 0 ? rem * 2 : 0);
            uint32_t o = SWZ64((uint32_t)(r * 64 + g * 16));
            const size_t so = (size_t)(nblk + r) * PITCH + kk;
            cpa16(base + AHI + o, Xhi + so, sz);
            cpa16(base + ALO + o, Xlo + so, sz);
        }
        #pragma unroll
        for (int i = 0; i < 2; i++) {
            int li = t + (i << 8);
            int r = li >> 2, g = li & 3;
            int row = cblk + r;
            int kk = k0 + g * 8, rem = cin - kk;
            int sz = (row < cout) ? (rem >= 8 ? 16 : (rem > 0 ? rem * 2 : 0)) : 0;
            uint32_t o = SWZ64((uint32_t)(r * 64 + g * 16));
            const size_t so = (size_t)row * wpitch + kk;
            cpa16(base + BHI + o, Wh + so, sz);
            cpa16(base + BLO + o, Wl + so, sz);
        }
        cpa_commit();
    };

    const int wm = wid >> 2, wn = wid & 3;
    const int seg = lane >> 3, i7 = lane & 7;
    uint32_t aR[4], aX[4];
    #pragma unroll
    for (int mi = 0; mi < 4; mi++) {
        int r = wm * 64 + mi * 16 + (seg & 1) * 8 + i7;
        aR[mi] = (uint32_t)(r * 64);
        aX[mi] = (aR[mi] >> 3) & 0x30;
    }
    const uint32_t akd = (uint32_t)((seg >> 1) * 16);
    uint32_t bR[2], bX[2];
    #pragma unroll
    for (int np = 0; np < 2; np++) {
        int r = wn * 32 + np * 16 + (seg >> 1) * 8 + i7;
        bR[np] = (uint32_t)(r * 64);
        bX[np] = (bR[np] >> 3) & 0x30;
    }
    const uint32_t bkd = (uint32_t)((seg & 1) * 16);

    float acc[4][4][4];
    #pragma unroll
    for (int mi = 0; mi < 4; mi++)
        #pragma unroll
        for (int ni = 0; ni < 4; ni++)
            #pragma unroll
            for (int r = 0; r < 4; r++) acc[mi][ni][r] = 0.f;

    auto compute = [&](int s) {
        const uint32_t base = sb + (uint32_t)s * STG_SZ;
        #pragma unroll
        for (int st = 0; st < 2; st++) {
            const uint32_t kb = (uint32_t)(st * 32);
            uint32_t Ah[4][4], Bh[2][4];
            #pragma unroll
            for (int mi = 0; mi < 4; mi++)
                ldsm4(Ah[mi], base + AHI + aR[mi] + ((kb + akd) ^ aX[mi]));
            #pragma unroll
            for (int np = 0; np < 2; np++)
                ldsm4(Bh[np], base + BHI + bR[np] + ((kb + bkd) ^ bX[np]));
            #pragma unroll
            for (int mi = 0; mi < 4; mi++)
                #pragma unroll
                for (int ni = 0; ni < 4; ni++)
                    mma_f16(acc[mi][ni], Ah[mi],
                            Bh[ni >> 1][(ni & 1) * 2], Bh[ni >> 1][(ni & 1) * 2 + 1]);
            {
                uint32_t Al[4][4];
                #pragma unroll
                for (int mi = 0; mi < 4; mi++)
                    ldsm4(Al[mi], base + ALO + aR[mi] + ((kb + akd) ^ aX[mi]));
                #pragma unroll
                for (int mi = 0; mi < 4; mi++)
                    #pragma unroll
                    for (int ni = 0; ni < 4; ni++)
                        mma_f16(acc[mi][ni], Al[mi],
                                Bh[ni >> 1][(ni & 1) * 2], Bh[ni >> 1][(ni & 1) * 2 + 1]);
            }
            {
                uint32_t Bl[2][4];
                #pragma unroll
                for (int np = 0; np < 2; np++)
                    ldsm4(Bl[np], base + BLO + bR[np] + ((kb + bkd) ^ bX[np]));
                #pragma unroll
                for (int mi = 0; mi < 4; mi++)
                    #pragma unroll
                    for (int ni = 0; ni < 4; ni++)
                        mma_f16(acc[mi][ni], Ah[mi],
                                Bl[ni >> 1][(ni & 1) * 2], Bl[ni >> 1][(ni & 1) * 2 + 1]);
            }
        }
    };

    load_stage(0, 0);
    if (ktiles > 1) load_stage(1, 1); else cpa_commit();
    for (int kt = 0; kt < ktiles; kt++) {
        asm volatile("cp.async.wait_group 1;" ::: "memory");
        __syncthreads();
        int nf = kt + 2;
        if (nf < ktiles) load_stage(nf % STAGES, nf); else cpa_commit();
        compute(kt % STAGES);
    }

    const int q = lane >> 2, c2 = (lane & 3) * 2;
    #pragma unroll
    for (int mi = 0; mi < 4; mi++) {
        int r0 = nblk + wm * 64 + mi * 16 + q;
        #pragma unroll
        for (int ni = 0; ni < 4; ni++) {
            int nloc = wn * 32 + ni * 8 + c2;
            int cg = cblk + nloc;
            float bv0 = bias_s[nloc], bv1 = bias_s[nloc + 1];
            const float* d = acc[mi][ni];
            #pragma unroll
            for (int rr = 0; rr < 2; rr++) {
                int r = r0 + rr * 8;
                float A0 = 100.f * (d[rr * 2] + bv0);
                float A1 = 100.f * (d[rr * 2 + 1] + bv1);
                float e0 = __expf(-fabsf(A0)), e1 = __expf(-fabsf(A1));
                float sp0 = (fmaxf(A0, 0.f) + __logf(1.f + e0)) * 0.01f;
                float sp1 = (fmaxf(A1, 0.f) + __logf(1.f + e1)) * 0.01f;
                float i0 = __fdividef(1.f, 1.f + e0);
                float i1 = __fdividef(1.f, 1.f + e1);
                float sg0 = (A0 >= 0.f) ? i0 : e0 * i0;
                float sg1 = (A1 >= 0.f) ? i1 : e1 * i1;
                __half h0, l0, h1, l1;
                split2h(sp0, h0, l0);
                split2h(sp1, h1, l1);
                __half* yh = Yhi + (size_t)r * PITCH;
                __half* yl = Ylo + (size_t)r * PITCH;
                float* gp = gate_wr + (size_t)r * PITCH;
                if (cg + 1 < cout) {
                    *(uint32_t*)(yh + cg) = (uint32_t)__half_as_ushort(h0)
                                          | ((uint32_t)__half_as_ushort(h1) << 16);
                    *(uint32_t*)(yl + cg) = (uint32_t)__half_as_ushort(l0)
                                          | ((uint32_t)__half_as_ushort(l1) << 16);
                    *(float2*)(gp + cg) = make_float2(sg0, sg1);
                } else if (cg < cout) {
                    yh[cg] = h0;
                    yl[cg] = l0;
                    gp[cg] = sg0;
                }
            }
        }
    }
}

// ===========================================================================
// reverse step: r = u · W_{j+1} (3-term, B = transposed weights, K=cout_j),
// epilogue: u' = r ⊙ gate[j-1]. rp = read parity (0 = A buffers).
// ===========================================================================
__global__ void __launch_bounds__(256, 2)
rev_kernel(int kdim, int ndim, int wtpit, size_t wtoff, size_t goff, int rp)
{
    extern __shared__ char smem[];
    const uint32_t sb = smem_u32(smem);
    const int t = threadIdx.x;
    const int lane = t & 31, wid = t >> 5;

    const __half* __restrict__ Uhi = rp ? g_uhiB : g_uhiA;
    const __half* __restrict__ Ulo = rp ? g_uloB : g_uloA;
    __half* __restrict__ Yhi = rp ? g_uhiA : g_uhiB;
    __half* __restrict__ Ylo = rp ? g_uloA : g_uloB;
    const float* __restrict__ gate_rd = g_gate + goff;
    const __half* __restrict__ Wh = g_Wthi + wtoff;
    const __half* __restrict__ Wl = g_Wtlo + wtoff;

    const int cblk = blockIdx.x * 128;   // over ndim (cin)
    const int nblk = blockIdx.y * 128;   // over points

    const int ktiles = kdim >> 5;        // kdim always /32

    auto load_stage = [&](int s, int kt) {
        const uint32_t base = sb + (uint32_t)s * STG_SZ;
        const int k0 = kt << 5;
        #pragma unroll
        for (int i = 0; i < 2; i++) {
            int li = t + (i << 8);
            int r = li >> 2, g = li & 3;
            int kk = k0 + g * 8;
            uint32_t o = SWZ64((uint32_t)(r * 64 + g * 16));
            const size_t so = (size_t)(nblk + r) * PITCH + kk;
            cpa16(base + AHI + o, Uhi + so, 16);
            cpa16(base + ALO + o, Ulo + so, 16);
        }
        #pragma unroll
        for (int i = 0; i < 2; i++) {
            int li = t + (i << 8);
            int r = li >> 2, g = li & 3;
            int row = cblk + r;
            int kk = k0 + g * 8;
            int sz = (row < ndim) ? 16 : 0;
            uint32_t o = SWZ64((uint32_t)(r * 64 + g * 16));
            const size_t so = (size_t)row * wtpit + kk;
            cpa16(base + BHI + o, Wh + so, sz);
            cpa16(base + BLO + o, Wl + so, sz);
        }
        cpa_commit();
    };

    const int wm = wid >> 2, wn = wid & 3;
    const int seg = lane >> 3, i7 = lane & 7;
    uint32_t aR[4], aX[4];
    #pragma unroll
    for (int mi = 0; mi < 4; mi++) {
        int r = wm * 64 + mi * 16 + (seg & 1) * 8 + i7;
        aR[mi] = (uint32_t)(r * 64);
        aX[mi] = (aR[mi] >> 3) & 0x30;
    }
    const uint32_t akd = (uint32_t)((seg >> 1) * 16);
    uint32_t bR[2], bX[2];
    #pragma unroll
    for (int np = 0; np < 2; np++) {
        int r = wn * 32 + np * 16 + (seg >> 1) * 8 + i7;
        bR[np] = (uint32_t)(r * 64);
        bX[np] = (bR[np] >> 3) & 0x30;
    }
    const uint32_t bkd = (uint32_t)((seg & 1) * 16);

    float acc[4][4][4];
    #pragma unroll
    for (int mi = 0; mi < 4; mi++)
        #pragma unroll
        for (int ni = 0; ni < 4; ni++)
            #pragma unroll
            for (int r = 0; r < 4; r++) acc[mi][ni][r] = 0.f;

    auto compute = [&](int s) {
        const uint32_t base = sb + (uint32_t)s * STG_SZ;
        #pragma unroll
        for (int st = 0; st < 2; st++) {
            const uint32_t kb = (uint32_t)(st * 32);
            uint32_t Ah[4][4], Bh[2][4];
            #pragma unroll
            for (int mi = 0; mi < 4; mi++)
                ldsm4(Ah[mi], base + AHI + aR[mi] + ((kb + akd) ^ aX[mi]));
            #pragma unroll
            for (int np = 0; np < 2; np++)
                ldsm4(Bh[np], base + BHI + bR[np] + ((kb + bkd) ^ bX[np]));
            #pragma unroll
            for (int mi = 0; mi < 4; mi++)
                #pragma unroll
                for (int ni = 0; ni < 4; ni++)
                    mma_f16(acc[mi][ni], Ah[mi],
                            Bh[ni >> 1][(ni & 1) * 2], Bh[ni >> 1][(ni & 1) * 2 + 1]);
            {
                uint32_t Al[4][4];
                #pragma unroll
                for (int mi = 0; mi < 4; mi++)
                    ldsm4(Al[mi], base + ALO + aR[mi] + ((kb + akd) ^ aX[mi]));
                #pragma unroll
                for (int mi = 0; mi < 4; mi++)
                    #pragma unroll
                    for (int ni = 0; ni < 4; ni++)
                        mma_f16(acc[mi][ni], Al[mi],
                                Bh[ni >> 1][(ni & 1) * 2], Bh[ni >> 1][(ni & 1) * 2 + 1]);
            }
            {
                uint32_t Bl[2][4];
                #pragma unroll
                for (int np = 0; np < 2; np++)
                    ldsm4(Bl[np], base + BLO + bR[np] + ((kb + bkd) ^ bX[np]));
                #pragma unroll
                for (int mi = 0; mi < 4; mi++)
                    #pragma unroll
                    for (int ni = 0; ni < 4; ni++)
                        mma_f16(acc[mi][ni], Ah[mi],
                                Bl[ni >> 1][(ni & 1) * 2], Bl[ni >> 1][(ni & 1) * 2 + 1]);
            }
        }
    };

    load_stage(0, 0);
    if (ktiles > 1) load_stage(1, 1); else cpa_commit();
    for (int kt = 0; kt < ktiles; kt++) {
        asm volatile("cp.async.wait_group 1;" ::: "memory");
        __syncthreads();
        int nf = kt + 2;
        if (nf < ktiles) load_stage(nf % STAGES, nf); else cpa_commit();
        compute(kt % STAGES);
    }

    // epilogue: u' = acc * gate[j-1][p][c]
    const int q = lane >> 2, c2 = (lane & 3) * 2;
    #pragma unroll
    for (int mi = 0; mi < 4; mi++) {
        int r0 = nblk + wm * 64 + mi * 16 + q;
        #pragma unroll
        for (int rr = 0; rr < 2; rr++) {
            int r = r0 + rr * 8;
            const float* gp = gate_rd + (size_t)r * PITCH;
            __half* yh = Yhi + (size_t)r * PITCH;
            __half* yl = Ylo + (size_t)r * PITCH;
            #pragma unroll
            for (int ni = 0; ni < 4; ni++) {
                int cg = cblk + wn * 32 + ni * 8 + c2;
                float d0 = acc[mi][ni][rr * 2], d1 = acc[mi][ni][rr * 2 + 1];
                if (cg + 1 < ndim) {
                    float2 sg = *(const float2*)(gp + cg);
                    __half h0, l0, h1, l1;
                    split2h(sg.x * d0, h0, l0);
                    split2h(sg.y * d1, h1, l1);
                    *(uint32_t*)(yh + cg) = (uint32_t)__half_as_ushort(h0)
                                          | ((uint32_t)__half_as_ushort(h1) << 16);
                    *(uint32_t*)(yl + cg) = (uint32_t)__half_as_ushort(l0)
                                          | ((uint32_t)__half_as_ushort(l1) << 16);
                } else if (cg < ndim) {
                    __half h0, l0;
                    split2h(gp[cg] * d0, h0, l0);
                    yh[cg] = h0;
                    yl[cg] = l0;
                }
            }
        }
    }
}

// ---- seed: u11 = W12 ⊙ gate[10]  (writes A buffers) -----------------------
__global__ void seed_kernel(const float* __restrict__ W12)
{
    int idx = blockIdx.x * blockDim.x + threadIdx.x;   // NPTS*896
    if (idx >= NPTS * 896) return;
    int p = idx / 896;
    int o = idx - p * 896;
    float v = __ldg(W12 + o) * g_gate[(size_t)10 * NPTS * PITCH
                                      + (size_t)p * PITCH + o];
    __half h, l;
    split2h(v, h, l);
    size_t d = (size_t)p * PITCH + o;
    g_uhiA[d] = h;
    g_uloA[d] = l;
}

// ---- final: z = W12·x11 + b; g = u1 · W1[:, 0:3] --------------------------
__global__ void final_kernel(const float* __restrict__ W12,
                             const float* __restrict__ b12,
                             const float* __restrict__ W1,
                             float* __restrict__ out)
{
    int gw = (blockIdx.x * blockDim.x + threadIdx.x) >> 5;
    int lane = threadIdx.x & 31;
    if (gw >= 2 * NPTS) return;
    if (gw < NPTS) {                         // z row
        const __half* hp = g_xhiB + (size_t)gw * PITCH;
        const __half* lp = g_xloB + (size_t)gw * PITCH;
        float s = 0.f;
        for (int i = lane; i < 112; i += 32) {   // 896 channels
            uint4 hv = *(const uint4*)(hp + i * 8);
            uint4 lv = *(const uint4*)(lp + i * 8);
            float4 w0 = __ldg((const float4*)W12 + i * 2);
            float4 w1 = __ldg((const float4*)W12 + i * 2 + 1);
            const uint32_t* hw = &hv.x;
            const uint32_t* lw = &lv.x;
            float wf2[8] = {w0.x, w0.y, w0.z, w0.w, w1.x, w1.y, w1.z, w1.w};
            #pragma unroll
            for (int qq = 0; qq < 4; qq++) {
                float2 fh = __half22float2(*(const __half2*)&hw[qq]);
                float2 fl = __half22float2(*(const __half2*)&lw[qq]);
                s = fmaf(wf2[2 * qq],     fh.x + fl.x, s);
                s = fmaf(wf2[2 * qq + 1], fh.y + fl.y, s);
            }
        }
        #pragma unroll
        for (int o = 16; o; o >>= 1) s += __shfl_xor_sync(0xffffffffu, s, o);
        if (lane == 0) out[gw] = s + b12[0];
    } else {                                 // gradient: u1 · W1[:,0:3]
        int p = gw - NPTS;
        const __half* hp = g_uhiA + (size_t)p * PITCH;
        const __half* lp = g_uloA + (size_t)p * PITCH;
        float s0 = 0.f, s1 = 0.f, s2 = 0.f;
        for (int o = lane; o < 515; o += 32) {
            float u = __half2float(hp[o]) + __half2float(lp[o]);
            const float* wr = W1 + (size_t)o * 259;
            s0 = fmaf(u, __ldg(wr),     s0);
            s1 = fmaf(u, __ldg(wr + 1), s1);
            s2 = fmaf(u, __ldg(wr + 2), s2);
        }
        #pragma unroll
        for (int o = 16; o; o >>= 1) {
            s0 += __shfl_xor_sync(0xffffffffu, s0, o);
            s1 += __shfl_xor_sync(0xffffffffu, s1, o);
            s2 += __shfl_xor_sync(0xffffffffu, s2, o);
        }
        if (lane == 0) {
            float* go = out + NPTS + 3 * (size_t)p;
            go[0] = s0; go[1] = s1; go[2] = s2;
        }
    }
}

// ---------------------------------------------------------------------------
extern "C" void kernel_launch(void* const* d_in, const int* in_sizes, int n_in,
                              void* d_out, int out_size)
{
    const float* input  = (const float*)d_in[0];
    const float* latent = (const float*)d_in[1];
    float* out = (float*)d_out;
    float* out_con = out + NPTS + NPTS * 3;

    {
        WPtrs wp;
        for (int l = 0; l < 11; l++) wp.w[l] = (const float*)d_in[2 + 2 * l];
        dim3 grid((960 * 960 + 255) / 256, 11);
        prep_all_kernel<<<grid, 256>>>(wp);
    }
    {
        int tot = NPTS * 259;
        init_kernel<<<(tot + 255) / 256, 256>>>(input, latent, out_con);
    }

    cudaFuncSetAttribute(x_kernel,
                         cudaFuncAttributeMaxDynamicSharedMemorySize, SMEM_BYTES);
    cudaFuncSetAttribute(rev_kernel,
                         cudaFuncAttributeMaxDynamicSharedMemorySize, SMEM_BYTES);

    // forward x-pass, storing all gates
    for (int l = 0; l < 11; l++) {
        const float* b = (const float*)d_in[3 + 2 * l];
        dim3 grid((LCOUT[l] + 127) / 128, NPTS / 128);
        x_kernel<<<grid, 256, SMEM_BYTES>>>(b, LCIN[l], LCOUT[l],
                                            LPIT[l], LWOFF[l],
                                            (size_t)l * NPTS * PITCH, l & 1);
    }

    // reverse sweep: seed u11, then j = 10 .. 1
    seed_kernel<<<(NPTS * 896 + 255) / 256, 256>>>((const float*)d_in[24]);
    for (int j = 10; j >= 1; j--) {
        int kdim = LCOUT[j];
        int ndim = LCIN[j];
        dim3 grid((ndim + 127) / 128, NPTS / 128);
        rev_kernel<<<grid, 256, SMEM_BYTES>>>(kdim, ndim, WTPIT[j], WTOFF[j],
                                              (size_t)(j - 1) * NPTS * PITCH,
                                              (10 - j) & 1);
    }

    final_kernel<<<2 * NPTS * 32 / 256, 256>>>((const float*)d_in[24],
                                               (const float*)d_in[25],
                                               (const float*)d_in[2], out);
}

// round 15
// speedup vs baseline: 2.9156x; 1.1168x over previous
#include <cuda_runtime.h>
#include <cuda_fp16.h>
#include <math.h>
#include <stdint.h>

// ===========================================================================
// ImplicitMap_fExtrator — Round 15: reverse-mode Jacobian, 2-term reverse.
// Forward x-pass: 3-term fp16 hi/lo split (gate-critical), stores all gates
// in fp32. Reverse pass: u stored SINGLE fp16; r = u·(Whi + Wlo) (2 terms),
// u' = r ⊙ gate (fp32 exact). FLOPs: 3 (x) + 1.94 (rev) = 4.94 units
// (was 5.9). Error budget: u fp16 quantization ~2^-12/layer × √10 ≈ 7e-4
// (r11 measured 7.3e-4 for the identical scheme — passes 1e-3).
// GEMM core = validated r7 config: Kc=32 x 3 stages, 64B XOR tiles, 256 thr,
// warp tile 64x32, 1 sync/iter, 2 CTAs/SM.
// ===========================================================================

#define NPTS   16384
#define PITCH  960

__device__ __half g_xhiA[(size_t)NPTS * PITCH];
__device__ __half g_xloA[(size_t)NPTS * PITCH];
__device__ __half g_xhiB[(size_t)NPTS * PITCH];
__device__ __half g_xloB[(size_t)NPTS * PITCH];
__device__ __half g_uA  [(size_t)NPTS * PITCH];
__device__ __half g_uB  [(size_t)NPTS * PITCH];
__device__ float  g_gate[(size_t)11 * NPTS * PITCH];     // all-layer gates
__device__ __half g_Whi [5600000];
__device__ __half g_Wlo [5600000];
__device__ __half g_Wthi[5600000];
__device__ __half g_Wtlo[5600000];

static const int    LCIN [11] = {259,515,512,512,576,576,768,768,768,960,960};
static const int    LCOUT[11] = {515,512,512,576,576,768,768,768,960,960,896};
static const int    LPIT [11] = {264,520,512,512,576,576,768,768,768,960,960};
static const size_t LWOFF[11] = {0,135960,402200,664344,959256,1291032,1733400,
                                 2323224,2913048,3650328,4571928};
static const int    WTPIT[11] = {520,512,512,576,576,768,768,768,960,960,896};
static const size_t WTOFF[11] = {0,134680,398360,660504,955416,1287192,1729560,
                                 2319384,2909208,3646488,4568088};

__device__ const int    d_LCIN [11] = {259,515,512,512,576,576,768,768,768,960,960};
__device__ const int    d_LCOUT[11] = {515,512,512,576,576,768,768,768,960,960,896};
__device__ const int    d_LPIT [11] = {264,520,512,512,576,576,768,768,768,960,960};
__device__ const size_t d_LWOFF[11] = {0,135960,402200,664344,959256,1291032,1733400,
                                       2323224,2913048,3650328,4571928};
__device__ const int    d_WTPIT[11] = {520,512,512,576,576,768,768,768,960,960,896};
__device__ const size_t d_WTOFF[11] = {0,134680,398360,660504,955416,1287192,1729560,
                                       2319384,2909208,3646488,4568088};

// ---- PTX helpers ----------------------------------------------------------
__device__ __forceinline__ uint32_t smem_u32(const void* p) {
    uint32_t a;
    asm("{ .reg .u64 t; cvta.to.shared.u64 t, %1; cvt.u32.u64 %0, t; }"
        : "=r"(a) : "l"(p));
    return a;
}
__device__ __forceinline__ void cpa16(uint32_t dst, const void* src, int sz) {
    asm volatile("cp.async.cg.shared.global [%0], [%1], 16, %2;"
                 :: "r"(dst), "l"(src), "r"(sz));
}
__device__ __forceinline__ void cpa_commit() {
    asm volatile("cp.async.commit_group;" ::: "memory");
}
__device__ __forceinline__ void ldsm4(uint32_t* r, uint32_t a) {
    asm volatile("ldmatrix.sync.aligned.m8n8.x4.shared.b16 {%0,%1,%2,%3}, [%4];"
                 : "=r"(r[0]), "=r"(r[1]), "=r"(r[2]), "=r"(r[3]) : "r"(a));
}
__device__ __forceinline__ void mma_f16(float* d, const uint32_t* a,
                                        uint32_t b0, uint32_t b1) {
    asm volatile("mma.sync.aligned.m16n8k16.row.col.f32.f16.f16.f32 "
                 "{%0,%1,%2,%3}, {%4,%5,%6,%7}, {%8,%9}, {%0,%1,%2,%3};"
                 : "+f"(d[0]), "+f"(d[1]), "+f"(d[2]), "+f"(d[3])
                 : "r"(a[0]), "r"(a[1]), "r"(a[2]), "r"(a[3]),
                   "r"(b0), "r"(b1));
}
__device__ __forceinline__ void split2h(float v, __half& h, __half& l) {
    h = __float2half_rn(v);
    l = __float2half_rn(v - __half2float(h));
}

// ---- fused W prep: forward (K-major cin) AND transposed (K-major cout) ----
struct WPtrs { const float* w[11]; };

__global__ void prep_all_kernel(WPtrs wp)
{
    int l = blockIdx.y;
    int idx = blockIdx.x * blockDim.x + threadIdx.x;
    int cin = d_LCIN[l];
    int cnt = cin * d_LCOUT[l];
    if (idx >= cnt) return;
    int row = idx / cin, col = idx - row * cin;
    __half h, lo;
    split2h(wp.w[l][idx], h, lo);
    size_t d = d_LWOFF[l] + (size_t)row * d_LPIT[l] + col;
    g_Whi[d] = h;
    g_Wlo[d] = lo;
    size_t dt = d_WTOFF[l] + (size_t)col * d_WTPIT[l] + row;
    g_Wthi[dt] = h;
    g_Wtlo[dt] = lo;
}

// ---- init ------------------------------------------------------------------
__global__ void init_kernel(const float* __restrict__ inp,
                            const float* __restrict__ lat,
                            float* __restrict__ out_con)
{
    int idx = blockIdx.x * blockDim.x + threadIdx.x;   // NPTS*259
    if (idx >= NPTS * 259) return;
    int p = idx / 259;
    int c = idx - p * 259;
    int b = p >> 13;
    float v = (c < 3) ? inp[p * 3 + c] : lat[b * 256 + (c - 3)];
    out_con[idx] = v;
    __half h, l;
    split2h(v, h, l);
    size_t xo = (size_t)p * PITCH + c;
    g_xhiA[xo] = h;
    g_xloA[xo] = l;
}

// ---- tile constants --------------------------------------------------------
#define STAGES 3
#define AHI 0
#define ALO 8192
#define BHI 16384
#define BLO 24576
#define STG_SZ 32768
#define SMEM_X (STAGES * STG_SZ)
// reverse stage: u single (8KB) + Bhi (8KB) + Blo (8KB)
#define RGA  0
#define RBHI 8192
#define RBLO 16384
#define STG_R 24576
#define SMEM_R (STAGES * STG_R)
#define SWZ64(o) ((o) ^ (((o) >> 3) & 0x30))

// ===========================================================================
// x-layer: 3-term split GEMM + softplus epilogue; gate -> g_gate[goff]
// ===========================================================================
__global__ void __launch_bounds__(256, 2)
x_kernel(const float* __restrict__ bias, int cin, int cout,
         int wpitch, size_t woff, size_t goff, int flip)
{
    extern __shared__ char smem[];
    __shared__ float bias_s[128];
    const uint32_t sb = smem_u32(smem);
    const int t = threadIdx.x;
    const int lane = t & 31, wid = t >> 5;

    const __half* __restrict__ Xhi = flip ? g_xhiB : g_xhiA;
    const __half* __restrict__ Xlo = flip ? g_xloB : g_xloA;
    __half* __restrict__ Yhi = flip ? g_xhiA : g_xhiB;
    __half* __restrict__ Ylo = flip ? g_xloA : g_xloB;
    float* __restrict__ gate_wr = g_gate + goff;
    const __half* __restrict__ Wh = g_Whi + woff;
    const __half* __restrict__ Wl = g_Wlo + woff;

    const int cblk = blockIdx.x * 128;
    const int nblk = blockIdx.y * 128;

    if (t < 128) {
        int c = cblk + t;
        bias_s[t] = (c < cout) ? __ldg(bias + c) : 0.f;
    }

    const int ktiles = (cin + 31) >> 5;

    auto load_stage = [&](int s, int kt) {
        const uint32_t base = sb + (uint32_t)s * STG_SZ;
        const int k0 = kt << 5;
        #pragma unroll
        for (int i = 0; i < 2; i++) {
            int li = t + (i << 8);
            int r = li >> 2, g = li & 3;
            int kk = k0 + g * 8, rem = cin - kk;
            int sz = rem >= 8 ? 16 : (rem > 0 ? rem * 2 : 0);
            uint32_t o = SWZ64((uint32_t)(r * 64 + g * 16));
            const size_t so = (size_t)(nblk + r) * PITCH + kk;
            cpa16(base + AHI + o, Xhi + so, sz);
            cpa16(base + ALO + o, Xlo + so, sz);
        }
        #pragma unroll
        for (int i = 0; i < 2; i++) {
            int li = t + (i << 8);
            int r = li >> 2, g = li & 3;
            int row = cblk + r;
            int kk = k0 + g * 8, rem = cin - kk;
            int sz = (row < cout) ? (rem >= 8 ? 16 : (rem > 0 ? rem * 2 : 0)) : 0;
            uint32_t o = SWZ64((uint32_t)(r * 64 + g * 16));
            const size_t so = (size_t)row * wpitch + kk;
            cpa16(base + BHI + o, Wh + so, sz);
            cpa16(base + BLO + o, Wl + so, sz);
        }
        cpa_commit();
    };

    const int wm = wid >> 2, wn = wid & 3;
    const int seg = lane >> 3, i7 = lane & 7;
    uint32_t aR[4], aX[4];
    #pragma unroll
    for (int mi = 0; mi < 4; mi++) {
        int r = wm * 64 + mi * 16 + (seg & 1) * 8 + i7;
        aR[mi] = (uint32_t)(r * 64);
        aX[mi] = (aR[mi] >> 3) & 0x30;
    }
    const uint32_t akd = (uint32_t)((seg >> 1) * 16);
    uint32_t bR[2], bX[2];
    #pragma unroll
    for (int np = 0; np < 2; np++) {
        int r = wn * 32 + np * 16 + (seg >> 1) * 8 + i7;
        bR[np] = (uint32_t)(r * 64);
        bX[np] = (bR[np] >> 3) & 0x30;
    }
    const uint32_t bkd = (uint32_t)((seg & 1) * 16);

    float acc[4][4][4];
    #pragma unroll
    for (int mi = 0; mi < 4; mi++)
        #pragma unroll
        for (int ni = 0; ni < 4; ni++)
            #pragma unroll
            for (int r = 0; r < 4; r++) acc[mi][ni][r] = 0.f;

    auto compute = [&](int s) {
        const uint32_t base = sb + (uint32_t)s * STG_SZ;
        #pragma unroll
        for (int st = 0; st < 2; st++) {
            const uint32_t kb = (uint32_t)(st * 32);
            uint32_t Ah[4][4], Bh[2][4];
            #pragma unroll
            for (int mi = 0; mi < 4; mi++)
                ldsm4(Ah[mi], base + AHI + aR[mi] + ((kb + akd) ^ aX[mi]));
            #pragma unroll
            for (int np = 0; np < 2; np++)
                ldsm4(Bh[np], base + BHI + bR[np] + ((kb + bkd) ^ bX[np]));
            #pragma unroll
            for (int mi = 0; mi < 4; mi++)
                #pragma unroll
                for (int ni = 0; ni < 4; ni++)
                    mma_f16(acc[mi][ni], Ah[mi],
                            Bh[ni >> 1][(ni & 1) * 2], Bh[ni >> 1][(ni & 1) * 2 + 1]);
            {
                uint32_t Al[4][4];
                #pragma unroll
                for (int mi = 0; mi < 4; mi++)
                    ldsm4(Al[mi], base + ALO + aR[mi] + ((kb + akd) ^ aX[mi]));
                #pragma unroll
                for (int mi = 0; mi < 4; mi++)
                    #pragma unroll
                    for (int ni = 0; ni < 4; ni++)
                        mma_f16(acc[mi][ni], Al[mi],
                                Bh[ni >> 1][(ni & 1) * 2], Bh[ni >> 1][(ni & 1) * 2 + 1]);
            }
            {
                uint32_t Bl[2][4];
                #pragma unroll
                for (int np = 0; np < 2; np++)
                    ldsm4(Bl[np], base + BLO + bR[np] + ((kb + bkd) ^ bX[np]));
                #pragma unroll
                for (int mi = 0; mi < 4; mi++)
                    #pragma unroll
                    for (int ni = 0; ni < 4; ni++)
                        mma_f16(acc[mi][ni], Ah[mi],
                                Bl[ni >> 1][(ni & 1) * 2], Bl[ni >> 1][(ni & 1) * 2 + 1]);
            }
        }
    };

    load_stage(0, 0);
    if (ktiles > 1) load_stage(1, 1); else cpa_commit();
    for (int kt = 0; kt < ktiles; kt++) {
        asm volatile("cp.async.wait_group 1;" ::: "memory");
        __syncthreads();
        int nf = kt + 2;
        if (nf < ktiles) load_stage(nf % STAGES, nf); else cpa_commit();
        compute(kt % STAGES);
    }

    const int q = lane >> 2, c2 = (lane & 3) * 2;
    #pragma unroll
    for (int mi = 0; mi < 4; mi++) {
        int r0 = nblk + wm * 64 + mi * 16 + q;
        #pragma unroll
        for (int ni = 0; ni < 4; ni++) {
            int nloc = wn * 32 + ni * 8 + c2;
            int cg = cblk + nloc;
            float bv0 = bias_s[nloc], bv1 = bias_s[nloc + 1];
            const float* d = acc[mi][ni];
            #pragma unroll
            for (int rr = 0; rr < 2; rr++) {
                int r = r0 + rr * 8;
                float A0 = 100.f * (d[rr * 2] + bv0);
                float A1 = 100.f * (d[rr * 2 + 1] + bv1);
                float e0 = __expf(-fabsf(A0)), e1 = __expf(-fabsf(A1));
                float sp0 = (fmaxf(A0, 0.f) + __logf(1.f + e0)) * 0.01f;
                float sp1 = (fmaxf(A1, 0.f) + __logf(1.f + e1)) * 0.01f;
                float i0 = __fdividef(1.f, 1.f + e0);
                float i1 = __fdividef(1.f, 1.f + e1);
                float sg0 = (A0 >= 0.f) ? i0 : e0 * i0;
                float sg1 = (A1 >= 0.f) ? i1 : e1 * i1;
                __half h0, l0, h1, l1;
                split2h(sp0, h0, l0);
                split2h(sp1, h1, l1);
                __half* yh = Yhi + (size_t)r * PITCH;
                __half* yl = Ylo + (size_t)r * PITCH;
                float* gp = gate_wr + (size_t)r * PITCH;
                if (cg + 1 < cout) {
                    *(uint32_t*)(yh + cg) = (uint32_t)__half_as_ushort(h0)
                                          | ((uint32_t)__half_as_ushort(h1) << 16);
                    *(uint32_t*)(yl + cg) = (uint32_t)__half_as_ushort(l0)
                                          | ((uint32_t)__half_as_ushort(l1) << 16);
                    *(float2*)(gp + cg) = make_float2(sg0, sg1);
                } else if (cg < cout) {
                    yh[cg] = h0;
                    yl[cg] = l0;
                    gp[cg] = sg0;
                }
            }
        }
    }
}

// ===========================================================================
// reverse step (2-term): r = u · (Wthi + Wtlo), u' = r ⊙ gate[j-1].
// u stored single fp16. rp = read parity (0 = A buffer).
// ===========================================================================
__global__ void __launch_bounds__(256, 2)
rev_kernel(int kdim, int ndim, int wtpit, size_t wtoff, size_t goff, int rp)
{
    extern __shared__ char smem[];
    const uint32_t sb = smem_u32(smem);
    const int t = threadIdx.x;
    const int lane = t & 31, wid = t >> 5;

    const __half* __restrict__ U = rp ? g_uB : g_uA;
    __half* __restrict__ Y = rp ? g_uA : g_uB;
    const float* __restrict__ gate_rd = g_gate + goff;
    const __half* __restrict__ Wh = g_Wthi + wtoff;
    const __half* __restrict__ Wl = g_Wtlo + wtoff;

    const int cblk = blockIdx.x * 128;   // over ndim (cin)
    const int nblk = blockIdx.y * 128;   // over points

    const int ktiles = kdim >> 5;        // kdim always /32

    auto load_stage = [&](int s, int kt) {
        const uint32_t base = sb + (uint32_t)s * STG_R;
        const int k0 = kt << 5;
        {   // A (u single): 512 granules, 2 per thread
            #pragma unroll
            for (int i = 0; i < 2; i++) {
                int li = t + (i << 8);
                int r = li >> 2, g = li & 3;
                int kk = k0 + g * 8;
                uint32_t o = SWZ64((uint32_t)(r * 64 + g * 16));
                cpa16(base + RGA + o, U + (size_t)(nblk + r) * PITCH + kk, 16);
            }
        }
        #pragma unroll
        for (int i = 0; i < 2; i++) {        // B hi/lo: 512 granules x2
            int li = t + (i << 8);
            int r = li >> 2, g = li & 3;
            int row = cblk + r;
            int kk = k0 + g * 8;
            int sz = (row < ndim) ? 16 : 0;
            uint32_t o = SWZ64((uint32_t)(r * 64 + g * 16));
            const size_t so = (size_t)row * wtpit + kk;
            cpa16(base + RBHI + o, Wh + so, sz);
            cpa16(base + RBLO + o, Wl + so, sz);
        }
        cpa_commit();
    };

    const int wm = wid >> 2, wn = wid & 3;
    const int seg = lane >> 3, i7 = lane & 7;
    uint32_t aR[4], aX[4];
    #pragma unroll
    for (int mi = 0; mi < 4; mi++) {
        int r = wm * 64 + mi * 16 + (seg & 1) * 8 + i7;
        aR[mi] = (uint32_t)(r * 64);
        aX[mi] = (aR[mi] >> 3) & 0x30;
    }
    const uint32_t akd = (uint32_t)((seg >> 1) * 16);
    uint32_t bR[2], bX[2];
    #pragma unroll
    for (int np = 0; np < 2; np++) {
        int r = wn * 32 + np * 16 + (seg >> 1) * 8 + i7;
        bR[np] = (uint32_t)(r * 64);
        bX[np] = (bR[np] >> 3) & 0x30;
    }
    const uint32_t bkd = (uint32_t)((seg & 1) * 16);

    float acc[4][4][4];
    #pragma unroll
    for (int mi = 0; mi < 4; mi++)
        #pragma unroll
        for (int ni = 0; ni < 4; ni++)
            #pragma unroll
            for (int r = 0; r < 4; r++) acc[mi][ni][r] = 0.f;

    auto compute = [&](int s) {
        const uint32_t base = sb + (uint32_t)s * STG_R;
        #pragma unroll
        for (int st = 0; st < 2; st++) {
            const uint32_t kb = (uint32_t)(st * 32);
            uint32_t Ah[4][4], Bh[2][4];
            #pragma unroll
            for (int mi = 0; mi < 4; mi++)
                ldsm4(Ah[mi], base + RGA + aR[mi] + ((kb + akd) ^ aX[mi]));
            #pragma unroll
            for (int np = 0; np < 2; np++)
                ldsm4(Bh[np], base + RBHI + bR[np] + ((kb + bkd) ^ bX[np]));
            #pragma unroll
            for (int mi = 0; mi < 4; mi++)
                #pragma unroll
                for (int ni = 0; ni < 4; ni++)
                    mma_f16(acc[mi][ni], Ah[mi],
                            Bh[ni >> 1][(ni & 1) * 2], Bh[ni >> 1][(ni & 1) * 2 + 1]);
            {
                uint32_t Bl[2][4];
                #pragma unroll
                for (int np = 0; np < 2; np++)
                    ldsm4(Bl[np], base + RBLO + bR[np] + ((kb + bkd) ^ bX[np]));
                #pragma unroll
                for (int mi = 0; mi < 4; mi++)
                    #pragma unroll
                    for (int ni = 0; ni < 4; ni++)
                        mma_f16(acc[mi][ni], Ah[mi],
                                Bl[ni >> 1][(ni & 1) * 2], Bl[ni >> 1][(ni & 1) * 2 + 1]);
            }
        }
    };

    load_stage(0, 0);
    if (ktiles > 1) load_stage(1, 1); else cpa_commit();
    for (int kt = 0; kt < ktiles; kt++) {
        asm volatile("cp.async.wait_group 1;" ::: "memory");
        __syncthreads();
        int nf = kt + 2;
        if (nf < ktiles) load_stage(nf % STAGES, nf); else cpa_commit();
        compute(kt % STAGES);
    }

    // epilogue: u' = acc * gate[j-1][p][c], single fp16
    const int q = lane >> 2, c2 = (lane & 3) * 2;
    #pragma unroll
    for (int mi = 0; mi < 4; mi++) {
        int r0 = nblk + wm * 64 + mi * 16 + q;
        #pragma unroll
        for (int rr = 0; rr < 2; rr++) {
            int r = r0 + rr * 8;
            const float* gp = gate_rd + (size_t)r * PITCH;
            __half* yr = Y + (size_t)r * PITCH;
            #pragma unroll
            for (int ni = 0; ni < 4; ni++) {
                int cg = cblk + wn * 32 + ni * 8 + c2;
                float d0 = acc[mi][ni][rr * 2], d1 = acc[mi][ni][rr * 2 + 1];
                if (cg + 1 < ndim) {
                    float2 sg = *(const float2*)(gp + cg);
                    __half h0 = __float2half_rn(sg.x * d0);
                    __half h1 = __float2half_rn(sg.y * d1);
                    *(uint32_t*)(yr + cg) = (uint32_t)__half_as_ushort(h0)
                                          | ((uint32_t)__half_as_ushort(h1) << 16);
                } else if (cg < ndim) {
                    yr[cg] = __float2half_rn(gp[cg] * d0);
                }
            }
        }
    }
}

// ---- seed: u11 = W12 ⊙ gate[10]  (writes A buffer) ------------------------
__global__ void seed_kernel(const float* __restrict__ W12)
{
    int idx = blockIdx.x * blockDim.x + threadIdx.x;   // NPTS*896
    if (idx >= NPTS * 896) return;
    int p = idx / 896;
    int o = idx - p * 896;
    float v = __ldg(W12 + o) * g_gate[(size_t)10 * NPTS * PITCH
                                      + (size_t)p * PITCH + o];
    g_uA[(size_t)p * PITCH + o] = __float2half_rn(v);
}

// ---- final: z = W12·x11 + b; g = u1 · W1[:, 0:3] --------------------------
__global__ void final_kernel(const float* __restrict__ W12,
                             const float* __restrict__ b12,
                             const float* __restrict__ W1,
                             float* __restrict__ out)
{
    int gw = (blockIdx.x * blockDim.x + threadIdx.x) >> 5;
    int lane = threadIdx.x & 31;
    if (gw >= 2 * NPTS) return;
    if (gw < NPTS) {                         // z row
        const __half* hp = g_xhiB + (size_t)gw * PITCH;
        const __half* lp = g_xloB + (size_t)gw * PITCH;
        float s = 0.f;
        for (int i = lane; i < 112; i += 32) {   // 896 channels
            uint4 hv = *(const uint4*)(hp + i * 8);
            uint4 lv = *(const uint4*)(lp + i * 8);
            float4 w0 = __ldg((const float4*)W12 + i * 2);
            float4 w1 = __ldg((const float4*)W12 + i * 2 + 1);
            const uint32_t* hw = &hv.x;
            const uint32_t* lw = &lv.x;
            float wf2[8] = {w0.x, w0.y, w0.z, w0.w, w1.x, w1.y, w1.z, w1.w};
            #pragma unroll
            for (int qq = 0; qq < 4; qq++) {
                float2 fh = __half22float2(*(const __half2*)&hw[qq]);
                float2 fl = __half22float2(*(const __half2*)&lw[qq]);
                s = fmaf(wf2[2 * qq],     fh.x + fl.x, s);
                s = fmaf(wf2[2 * qq + 1], fh.y + fl.y, s);
            }
        }
        #pragma unroll
        for (int o = 16; o; o >>= 1) s += __shfl_xor_sync(0xffffffffu, s, o);
        if (lane == 0) out[gw] = s + b12[0];
    } else {                                 // gradient: u1 · W1[:,0:3]
        int p = gw - NPTS;
        const __half* hp = g_uA + (size_t)p * PITCH;   // j=1 writes A
        float s0 = 0.f, s1 = 0.f, s2 = 0.f;
        for (int o = lane; o < 515; o += 32) {
            float u = __half2float(hp[o]);
            const float* wr = W1 + (size_t)o * 259;
            s0 = fmaf(u, __ldg(wr),     s0);
            s1 = fmaf(u, __ldg(wr + 1), s1);
            s2 = fmaf(u, __ldg(wr + 2), s2);
        }
        #pragma unroll
        for (int o = 16; o; o >>= 1) {
            s0 += __shfl_xor_sync(0xffffffffu, s0, o);
            s1 += __shfl_xor_sync(0xffffffffu, s1, o);
            s2 += __shfl_xor_sync(0xffffffffu, s2, o);
        }
        if (lane == 0) {
            float* go = out + NPTS + 3 * (size_t)p;
            go[0] = s0; go[1] = s1; go[2] = s2;
        }
    }
}

// ---------------------------------------------------------------------------
extern "C" void kernel_launch(void* const* d_in, const int* in_sizes, int n_in,
                              void* d_out, int out_size)
{
    const float* input  = (const float*)d_in[0];
    const float* latent = (const float*)d_in[1];
    float* out = (float*)d_out;
    float* out_con = out + NPTS + NPTS * 3;

    {
        WPtrs wp;
        for (int l = 0; l < 11; l++) wp.w[l] = (const float*)d_in[2 + 2 * l];
        dim3 grid((960 * 960 + 255) / 256, 11);
        prep_all_kernel<<<grid, 256>>>(wp);
    }
    {
        int tot = NPTS * 259;
        init_kernel<<<(tot + 255) / 256, 256>>>(input, latent, out_con);
    }

    cudaFuncSetAttribute(x_kernel,
                         cudaFuncAttributeMaxDynamicSharedMemorySize, SMEM_X);
    cudaFuncSetAttribute(rev_kernel,
                         cudaFuncAttributeMaxDynamicSharedMemorySize, SMEM_R);

    // forward x-pass, storing all gates
    for (int l = 0; l < 11; l++) {
        const float* b = (const float*)d_in[3 + 2 * l];
        dim3 grid((LCOUT[l] + 127) / 128, NPTS / 128);
        x_kernel<<<grid, 256, SMEM_X>>>(b, LCIN[l], LCOUT[l],
                                        LPIT[l], LWOFF[l],
                                        (size_t)l * NPTS * PITCH, l & 1);
    }

    // reverse sweep: seed u11, then j = 10 .. 1
    seed_kernel<<<(NPTS * 896 + 255) / 256, 256>>>((const float*)d_in[24]);
    for (int j = 10; j >= 1; j--) {
        int kdim = LCOUT[j];
        int ndim = LCIN[j];
        dim3 grid((ndim + 127) / 128, NPTS / 128);
        rev_kernel<<<grid, 256, SMEM_R>>>(kdim, ndim, WTPIT[j], WTOFF[j],
                                          (size_t)(j - 1) * NPTS * PITCH,
                                          (10 - j) & 1);
    }

    final_kernel<<<2 * NPTS * 32 / 256, 256>>>((const float*)d_in[24],
                                               (const float*)d_in[25],
                                               (const float*)d_in[2], out);
}